// round 1
// baseline (speedup 1.0000x reference)
#include <cuda_runtime.h>
#include <math.h>

// ---------------------------------------------------------------------------
// Problem constants
// ---------------------------------------------------------------------------
#define C_DIM   512
#define TDIM    8
#define HDIM    32
#define WDIM    32
#define SPATIAL 8192            // T*H*W
#define GROUPS  32
#define CPG     16              // channels per group
#define TP      10              // padded T (2,0)
#define HP      34              // padded H (1,1)
#define WP      34              // padded W (1,1)
#define PADN    (TP*HP*WP)      // 11560

// ---------------------------------------------------------------------------
// Scratch (device globals; no runtime allocation allowed)
// ---------------------------------------------------------------------------
__device__ float g_bufA[C_DIM * SPATIAL];
__device__ float g_bufB[C_DIM * SPATIAL];
__device__ float g_padbuf[C_DIM * PADN];
__device__ float g_q[SPATIAL * C_DIM];
__device__ float g_k[SPATIAL * C_DIM];
__device__ float g_v[SPATIAL * C_DIM];
__device__ float g_ao[SPATIAL * C_DIM];
__device__ float g_scores[(size_t)SPATIAL * SPATIAL];   // 256 MB

// ---------------------------------------------------------------------------
// GroupNorm (+ optional SiLU).  Input/output layout (C, SPATIAL).
// One block per group (32 blocks x 1024 threads), two passes.
// ---------------------------------------------------------------------------
__global__ void gn_kernel(const float* __restrict__ in, float* __restrict__ out,
                          const float* __restrict__ scale, const float* __restrict__ bias,
                          int do_silu)
{
    const int group = blockIdx.x;
    const int n = CPG * SPATIAL;                 // 131072
    const float* gin = in + (size_t)group * n;
    float* gout = out + (size_t)group * n;

    float sum = 0.f, sq = 0.f;
    for (int i = threadIdx.x; i < n; i += blockDim.x) {
        float v = gin[i];
        sum += v;
        sq += v * v;
    }
    __shared__ float ssum[32], ssq[32];
    for (int o = 16; o; o >>= 1) {
        sum += __shfl_xor_sync(0xffffffffu, sum, o);
        sq  += __shfl_xor_sync(0xffffffffu, sq,  o);
    }
    const int wid = threadIdx.x >> 5, lid = threadIdx.x & 31;
    if (lid == 0) { ssum[wid] = sum; ssq[wid] = sq; }
    __syncthreads();
    const int nw = blockDim.x >> 5;
    if (wid == 0) {
        sum = (lid < nw) ? ssum[lid] : 0.f;
        sq  = (lid < nw) ? ssq[lid]  : 0.f;
        for (int o = 16; o; o >>= 1) {
            sum += __shfl_xor_sync(0xffffffffu, sum, o);
            sq  += __shfl_xor_sync(0xffffffffu, sq,  o);
        }
        if (lid == 0) { ssum[0] = sum; ssq[0] = sq; }
    }
    __syncthreads();
    const float mu   = ssum[0] / (float)n;
    const float var  = ssq[0] / (float)n - mu * mu;
    const float rstd = rsqrtf(var + 1e-6f);

    for (int i = threadIdx.x; i < n; i += blockDim.x) {
        const int c = group * CPG + (i >> 13);   // i / 8192
        float v = (gin[i] - mu) * rstd * scale[c] + bias[c];
        if (do_silu) v = v / (1.f + __expf(-v));
        gout[i] = v;
    }
}

// ---------------------------------------------------------------------------
// Edge-replicate pad: (C, 8, 32, 32) -> (C, 10, 34, 34)
// time pad (2,0), spatial pad (1,1), all replicate.
// ---------------------------------------------------------------------------
__global__ void pad_kernel(const float* __restrict__ in, float* __restrict__ out)
{
    int idx = blockIdx.x * blockDim.x + threadIdx.x;
    if (idx >= C_DIM * PADN) return;
    int ci = idx / PADN;
    int r = idx - ci * PADN;
    int tp = r / (HP * WP); r -= tp * (HP * WP);
    int yp = r / WP;
    int xp = r - yp * WP;
    int t = tp - 2; if (t < 0) t = 0;
    int y = yp - 1; if (y < 0) y = 0; if (y > HDIM - 1) y = HDIM - 1;
    int x = xp - 1; if (x < 0) x = 0; if (x > WDIM - 1) x = WDIM - 1;
    out[idx] = in[((ci * TDIM + t) * HDIM + y) * WDIM + x];
}

// ---------------------------------------------------------------------------
// Conv3d 3x3x3 (VALID on padded input) + bias + optional residual.
// Implicit GEMM: out[co][t,y,x] over K = 512ci * 27 taps.
// Block: 64 co x 256 positions (one t, 8 rows y, full x).  256 threads,
// per-thread register tile 4co x 16x.
// Grid: (8 co-tiles, 32 spatial tiles:  t = by>>2, y0 = (by&3)*8)
// ---------------------------------------------------------------------------
__global__ __launch_bounds__(256, 2)
void conv_kernel(const float* __restrict__ P, const float* __restrict__ W,
                 const float* __restrict__ bias, const float* __restrict__ resid,
                 float* __restrict__ out)
{
    const int co0 = blockIdx.x * 64;
    const int t   = blockIdx.y >> 2;
    const int y0  = (blockIdx.y & 3) * 8;
    const int tid = threadIdx.x;
    const int tx  = tid & 15;           // position group
    const int ty  = tid >> 4;           // co group (0..15)
    const int row = tx >> 1;            // output row 0..7
    const int x0  = (tx & 1) * 16;      // output x base (0 or 16)

    __shared__ float sA[8][9][64];      // [ci][ky*3+kx][co]
    __shared__ float sB[8][10][35];     // [ci][padded row][padded x], stride 35 (bank-conflict-free)

    float acc[4][16];
#pragma unroll
    for (int i = 0; i < 4; i++)
#pragma unroll
        for (int j = 0; j < 16; j++) acc[i][j] = 0.f;

    for (int kt = 0; kt < 3; kt++) {
        const int tplane = (t + kt) * (HP * WP);
        for (int c0 = 0; c0 < C_DIM; c0 += 8) {
            // ---- load weights: 8 ci x 9 (ky,kx) x 64 co = 4608 ----
            for (int i = tid; i < 8 * 9 * 64; i += 256) {
                int ci = i / 576;
                int r2 = i - ci * 576;
                int kk = r2 >> 6;            // ky*3+kx
                int co = r2 & 63;
                sA[ci][kk][co] =
                    W[(size_t)((co0 + co) * C_DIM + (c0 + ci)) * 27 + kt * 9 + kk];
            }
            // ---- load padded input: 8 ci x 10 rows x 34 = 2720 ----
            for (int i = tid; i < 8 * 10 * 34; i += 256) {
                int ci = i / 340;
                int r2 = i - ci * 340;
                int ry = r2 / 34;
                int xx = r2 - ry * 34;
                sB[ci][ry][xx] =
                    P[(size_t)(c0 + ci) * PADN + tplane + (y0 + ry) * WP + xx];
            }
            __syncthreads();

            for (int ci = 0; ci < 8; ci++) {
#pragma unroll
                for (int ky = 0; ky < 3; ky++) {
                    float b[18];
#pragma unroll
                    for (int j = 0; j < 18; j++) b[j] = sB[ci][row + ky][x0 + j];
#pragma unroll
                    for (int kx = 0; kx < 3; kx++) {
                        const float a0 = sA[ci][ky * 3 + kx][ty * 4 + 0];
                        const float a1 = sA[ci][ky * 3 + kx][ty * 4 + 1];
                        const float a2 = sA[ci][ky * 3 + kx][ty * 4 + 2];
                        const float a3 = sA[ci][ky * 3 + kx][ty * 4 + 3];
#pragma unroll
                        for (int px = 0; px < 16; px++) {
                            const float bv = b[px + kx];
                            acc[0][px] += a0 * bv;
                            acc[1][px] += a1 * bv;
                            acc[2][px] += a2 * bv;
                            acc[3][px] += a3 * bv;
                        }
                    }
                }
            }
            __syncthreads();
        }
    }

    // ---- epilogue: bias + optional residual ----
    const int n_base = t * 1024 + (y0 + row) * 32 + x0;
#pragma unroll
    for (int i = 0; i < 4; i++) {
        const int co = co0 + ty * 4 + i;
        const float bb = bias[co];
        const size_t obase = (size_t)co * SPATIAL + n_base;
#pragma unroll
        for (int px = 0; px < 16; px++) {
            float v = acc[i][px] + bb;
            if (resid) v += resid[obase + px];
            out[obase + px] = v;
        }
    }
}

// ---------------------------------------------------------------------------
// Generic strided SGEMM:  C[m,n] = alpha * sum_k A(m,k) * B(k,n)  (+bias/resid)
// A element: A[m*Asm + k*Ask], B element: B[k*Bsk + n*Bsn], C: C[m*Csm + n*Csn]
// BM=128, BN=64, BK=16, 256 threads, per-thread 8x4.
// mode 0: plain; 1: K clipped to causal prefix of m-tile (AV);
// mode 2: skip tile entirely if key-frame > query-frame (masked scores).
// All dims must be multiples of the tile sizes (true here).
// ---------------------------------------------------------------------------
__global__ __launch_bounds__(256, 2)
void sgemm_kernel(const float* __restrict__ A, const float* __restrict__ B,
                  float* __restrict__ C,
                  int M, int N, int K,
                  int Asm, int Ask, int Bsk, int Bsn, int Csm, int Csn,
                  float alpha,
                  const float* __restrict__ biasM, const float* __restrict__ biasN,
                  const float* __restrict__ resid,
                  int mode)
{
    const int m0 = blockIdx.y * 128;
    const int n0 = blockIdx.x * 64;
    if (mode == 2 && ((n0 >> 10) > (m0 >> 10))) return;   // fully masked tile
    int Keff = K;
    if (mode == 1) {
        int lim = ((m0 >> 10) + 1) << 10;
        if (lim < Keff) Keff = lim;
    }

    __shared__ float sA[16][129];
    __shared__ float sB[16][65];

    const int tid = threadIdx.x;
    const int tx = tid & 15;      // n
    const int ty = tid >> 4;      // m
    const int mt = ty * 8;
    const int nt = tx * 4;

    float acc[8][4];
#pragma unroll
    for (int i = 0; i < 8; i++)
#pragma unroll
        for (int j = 0; j < 4; j++) acc[i][j] = 0.f;

    for (int k0 = 0; k0 < Keff; k0 += 16) {
        if (Ask == 1) {
            for (int i = tid; i < 2048; i += 256) {
                int kk = i & 15, mm = i >> 4;
                sA[kk][mm] = A[(size_t)(m0 + mm) * Asm + (k0 + kk)];
            }
        } else {
            for (int i = tid; i < 2048; i += 256) {
                int mm = i & 127, kk = i >> 7;
                sA[kk][mm] = A[(size_t)(m0 + mm) * Asm + (size_t)(k0 + kk) * Ask];
            }
        }
        if (Bsn == 1) {
            for (int i = tid; i < 1024; i += 256) {
                int nn = i & 63, kk = i >> 6;
                sB[kk][nn] = B[(size_t)(k0 + kk) * Bsk + (n0 + nn)];
            }
        } else {
            for (int i = tid; i < 1024; i += 256) {
                int kk = i & 15, nn = i >> 4;
                sB[kk][nn] = B[(size_t)(k0 + kk) * Bsk + (size_t)(n0 + nn) * Bsn];
            }
        }
        __syncthreads();
#pragma unroll
        for (int kk = 0; kk < 16; kk++) {
            const float b0 = sB[kk][nt + 0];
            const float b1 = sB[kk][nt + 1];
            const float b2 = sB[kk][nt + 2];
            const float b3 = sB[kk][nt + 3];
#pragma unroll
            for (int i = 0; i < 8; i++) {
                const float a = sA[kk][mt + i];
                acc[i][0] += a * b0;
                acc[i][1] += a * b1;
                acc[i][2] += a * b2;
                acc[i][3] += a * b3;
            }
        }
        __syncthreads();
    }

#pragma unroll
    for (int i = 0; i < 8; i++) {
        const int m = m0 + mt + i;
        const float bm = biasM ? biasM[m] : 0.f;
#pragma unroll
        for (int j = 0; j < 4; j++) {
            const int n = n0 + nt + j;
            float v = acc[i][j] * alpha + bm;
            if (biasN) v += biasN[n];
            const size_t cidx = (size_t)m * Csm + (size_t)n * Csn;
            if (resid) v += resid[cidx];
            C[cidx] = v;
        }
    }
}

// ---------------------------------------------------------------------------
// Row softmax over causal prefix L = ((q>>10)+1)*1024, in place on g_scores.
// ---------------------------------------------------------------------------
__global__ void softmax_kernel(float* __restrict__ S)
{
    const int q = blockIdx.x;
    const int L = ((q >> 10) + 1) << 10;
    float* row = S + (size_t)q * SPATIAL;
    __shared__ float red[32];
    const int wid = threadIdx.x >> 5, lid = threadIdx.x & 31;
    const int nw = blockDim.x >> 5;

    float mx = -1e30f;
    for (int i = threadIdx.x; i < L; i += blockDim.x) mx = fmaxf(mx, row[i]);
    for (int o = 16; o; o >>= 1) mx = fmaxf(mx, __shfl_xor_sync(0xffffffffu, mx, o));
    if (lid == 0) red[wid] = mx;
    __syncthreads();
    if (wid == 0) {
        float v = (lid < nw) ? red[lid] : -1e30f;
        for (int o = 16; o; o >>= 1) v = fmaxf(v, __shfl_xor_sync(0xffffffffu, v, o));
        if (lid == 0) red[0] = v;
    }
    __syncthreads();
    mx = red[0];
    __syncthreads();

    float sum = 0.f;
    for (int i = threadIdx.x; i < L; i += blockDim.x) {
        float e = __expf(row[i] - mx);
        row[i] = e;
        sum += e;
    }
    for (int o = 16; o; o >>= 1) sum += __shfl_xor_sync(0xffffffffu, sum, o);
    if (lid == 0) red[wid] = sum;
    __syncthreads();
    if (wid == 0) {
        float v = (lid < nw) ? red[lid] : 0.f;
        for (int o = 16; o; o >>= 1) v += __shfl_xor_sync(0xffffffffu, v, o);
        if (lid == 0) red[0] = v;
    }
    __syncthreads();
    const float inv = 1.f / red[0];
    for (int i = threadIdx.x; i < L; i += blockDim.x) row[i] *= inv;
}

// ---------------------------------------------------------------------------
// Host orchestration
// ---------------------------------------------------------------------------
extern "C" void kernel_launch(void* const* d_in, const int* in_sizes, int n_in,
                              void* d_out, int out_size)
{
    (void)in_sizes; (void)n_in; (void)out_size;

    const float* x      = (const float*)d_in[0];
    const float* r0_n1s = (const float*)d_in[1];
    const float* r0_n1b = (const float*)d_in[2];
    const float* r0_w1  = (const float*)d_in[3];
    const float* r0_b1  = (const float*)d_in[4];
    const float* r0_n2s = (const float*)d_in[5];
    const float* r0_n2b = (const float*)d_in[6];
    const float* r0_w2  = (const float*)d_in[7];
    const float* r0_b2  = (const float*)d_in[8];
    const float* r1_n1s = (const float*)d_in[9];
    const float* r1_n1b = (const float*)d_in[10];
    const float* r1_w1  = (const float*)d_in[11];
    const float* r1_b1  = (const float*)d_in[12];
    const float* r1_n2s = (const float*)d_in[13];
    const float* r1_n2b = (const float*)d_in[14];
    const float* r1_w2  = (const float*)d_in[15];
    const float* r1_b2  = (const float*)d_in[16];
    const float* a_gns  = (const float*)d_in[17];
    const float* a_gnb  = (const float*)d_in[18];
    const float* a_wq   = (const float*)d_in[19];
    const float* a_bq   = (const float*)d_in[20];
    const float* a_wk   = (const float*)d_in[21];
    const float* a_bk   = (const float*)d_in[22];
    const float* a_wv   = (const float*)d_in[23];
    const float* a_bv   = (const float*)d_in[24];
    const float* a_wo   = (const float*)d_in[25];
    const float* a_bo   = (const float*)d_in[26];
    float* out = (float*)d_out;

    float *bufA, *bufB, *padb, *qb, *kb, *vb, *aob, *sb;
    cudaGetSymbolAddress((void**)&bufA, g_bufA);
    cudaGetSymbolAddress((void**)&bufB, g_bufB);
    cudaGetSymbolAddress((void**)&padb, g_padbuf);
    cudaGetSymbolAddress((void**)&qb,   g_q);
    cudaGetSymbolAddress((void**)&kb,   g_k);
    cudaGetSymbolAddress((void**)&vb,   g_v);
    cudaGetSymbolAddress((void**)&aob,  g_ao);
    cudaGetSymbolAddress((void**)&sb,   g_scores);

    const int padGrid = (C_DIM * PADN + 255) / 256;
    const dim3 convGrid(8, 32);
    const float att_scale = 0.04419417382415922f;   // 512^-0.5

    // ---------------- resnet block 0 ----------------
    gn_kernel<<<GROUPS, 1024>>>(x, bufA, r0_n1s, r0_n1b, 1);
    pad_kernel<<<padGrid, 256>>>(bufA, padb);
    conv_kernel<<<convGrid, 256>>>(padb, r0_w1, r0_b1, nullptr, bufB);
    gn_kernel<<<GROUPS, 1024>>>(bufB, bufA, r0_n2s, r0_n2b, 1);
    pad_kernel<<<padGrid, 256>>>(bufA, padb);
    conv_kernel<<<convGrid, 256>>>(padb, r0_w2, r0_b2, x, bufB);   // bufB = h0

    // ---------------- attention ----------------
    gn_kernel<<<GROUPS, 1024>>>(bufB, bufA, a_gns, a_gnb, 0);      // bufA = xn (c,s)
    // q/k/v: [s, o] = sum_c xn[c,s] * w[o,c] + b[o]
    {
        dim3 g(C_DIM / 64, SPATIAL / 128);
        sgemm_kernel<<<g, 256>>>(bufA, a_wq, qb, SPATIAL, C_DIM, C_DIM,
                                 1, SPATIAL, 1, C_DIM, C_DIM, 1,
                                 1.f, nullptr, a_bq, nullptr, 0);
        sgemm_kernel<<<g, 256>>>(bufA, a_wk, kb, SPATIAL, C_DIM, C_DIM,
                                 1, SPATIAL, 1, C_DIM, C_DIM, 1,
                                 1.f, nullptr, a_bk, nullptr, 0);
        sgemm_kernel<<<g, 256>>>(bufA, a_wv, vb, SPATIAL, C_DIM, C_DIM,
                                 1, SPATIAL, 1, C_DIM, C_DIM, 1,
                                 1.f, nullptr, a_bv, nullptr, 0);
    }
    // scores[q,k] = scale * sum_d Q[q,d] K[k,d]   (skip masked tiles)
    {
        dim3 g(SPATIAL / 64, SPATIAL / 128);
        sgemm_kernel<<<g, 256>>>(qb, kb, sb, SPATIAL, SPATIAL, C_DIM,
                                 C_DIM, 1, 1, C_DIM, SPATIAL, 1,
                                 att_scale, nullptr, nullptr, nullptr, 2);
    }
    softmax_kernel<<<SPATIAL, 256>>>(sb);
    // AO[q,d] = sum_k P[q,k] V[k,d]   (K limited to causal prefix)
    {
        dim3 g(C_DIM / 64, SPATIAL / 128);
        sgemm_kernel<<<g, 256>>>(sb, vb, aob, SPATIAL, C_DIM, SPATIAL,
                                 SPATIAL, 1, C_DIM, 1, C_DIM, 1,
                                 1.f, nullptr, nullptr, nullptr, 1);
    }
    // h1[c,s] = h0[c,s] + bo[c] + sum_d AO[s,d] * wo[c,d]
    {
        dim3 g(SPATIAL / 64, C_DIM / 128);
        sgemm_kernel<<<g, 256>>>(a_wo, aob, bufA, C_DIM, SPATIAL, C_DIM,
                                 C_DIM, 1, 1, C_DIM, SPATIAL, 1,
                                 1.f, a_bo, nullptr, bufB, 0);      // bufA = h1
    }

    // ---------------- resnet block 1 ----------------
    gn_kernel<<<GROUPS, 1024>>>(bufA, bufB, r1_n1s, r1_n1b, 1);
    pad_kernel<<<padGrid, 256>>>(bufB, padb);
    conv_kernel<<<convGrid, 256>>>(padb, r1_w1, r1_b1, nullptr, bufB);
    gn_kernel<<<GROUPS, 1024>>>(bufB, qb, r1_n2s, r1_n2b, 1);      // reuse q buffer
    pad_kernel<<<padGrid, 256>>>(qb, padb);
    conv_kernel<<<convGrid, 256>>>(padb, r1_w2, r1_b2, bufA, out); // out = h1 + conv
}

// round 7
// speedup vs baseline: 1.0479x; 1.0479x over previous
#include <cuda_runtime.h>
#include <math.h>

// ---------------------------------------------------------------------------
// Problem constants
// ---------------------------------------------------------------------------
#define C_DIM   512
#define TDIM    8
#define HDIM    32
#define WDIM    32
#define SPATIAL 8192            // T*H*W
#define GROUPS  32
#define CPG     16              // channels per group
#define TP      10              // padded T (2,0)
#define HP      34              // padded H (1,1)
#define WP      34              // padded W (1,1)
#define PADN    (TP*HP*WP)      // 11560

typedef unsigned long long u64;

// ---------------------------------------------------------------------------
// Packed f32x2 helpers (sm_103a: fma.rn.f32x2 doubles fp32 FMA throughput;
// pack/unpack movs ride the alu pipe in parallel with the fma pipe).
// ---------------------------------------------------------------------------
__device__ __forceinline__ u64 pk2(float lo, float hi) {
    u64 r; asm("mov.b64 %0, {%1, %2};" : "=l"(r) : "f"(lo), "f"(hi)); return r;
}
__device__ __forceinline__ u64 dup2(float v) {
    u64 r; asm("mov.b64 %0, {%1, %1};" : "=l"(r) : "f"(v)); return r;
}
__device__ __forceinline__ void fma2(u64& d, u64 a, u64 b) {
    asm("fma.rn.f32x2 %0, %1, %2, %0;" : "+l"(d) : "l"(a), "l"(b));
}
__device__ __forceinline__ float2 upk2(u64 v) {
    float2 f; asm("mov.b64 {%0, %1}, %2;" : "=f"(f.x), "=f"(f.y) : "l"(v)); return f;
}

// ---------------------------------------------------------------------------
// Scratch (device globals; no runtime allocation allowed)
// ---------------------------------------------------------------------------
__device__ float g_bufA[C_DIM * SPATIAL];
__device__ float g_bufB[C_DIM * SPATIAL];
__device__ float g_padbuf[C_DIM * PADN];
__device__ float g_q[SPATIAL * C_DIM];
__device__ float g_k[SPATIAL * C_DIM];
__device__ float g_v[SPATIAL * C_DIM];
__device__ float g_ao[SPATIAL * C_DIM];
__device__ float g_part[256 * 2];                        // GN partial sums
__device__ float g_scores[(size_t)SPATIAL * SPATIAL];    // 256 MB

// ---------------------------------------------------------------------------
// GroupNorm pass 1: partial sums.  grid = 32 groups * 8 chunks = 256 blocks.
// ---------------------------------------------------------------------------
__global__ void gn_stats_kernel(const float* __restrict__ in)
{
    const int blk = blockIdx.x;                  // group*8 + chunk
    const float4* p = (const float4*)(in + (size_t)blk * 16384);
    float sum = 0.f, sq = 0.f;
    for (int i = threadIdx.x; i < 4096; i += 256) {
        float4 v = p[i];
        sum += v.x + v.y + v.z + v.w;
        sq  += v.x*v.x + v.y*v.y + v.z*v.z + v.w*v.w;
    }
    __shared__ float ss[8], sg[8];
    for (int o = 16; o; o >>= 1) {
        sum += __shfl_xor_sync(0xffffffffu, sum, o);
        sq  += __shfl_xor_sync(0xffffffffu, sq,  o);
    }
    const int wid = threadIdx.x >> 5, lid = threadIdx.x & 31;
    if (lid == 0) { ss[wid] = sum; sg[wid] = sq; }
    __syncthreads();
    if (threadIdx.x == 0) {
        float a = 0.f, b = 0.f;
        for (int w = 0; w < 8; w++) { a += ss[w]; b += sg[w]; }
        g_part[blk * 2 + 0] = a;
        g_part[blk * 2 + 1] = b;
    }
}

// ---------------------------------------------------------------------------
// GroupNorm pass 2: normalize (+ optional SiLU).  grid 4096 x 256.
// ---------------------------------------------------------------------------
__global__ void gn_apply_kernel(const float* __restrict__ in, float* __restrict__ out,
                                const float* __restrict__ scale, const float* __restrict__ bias,
                                int do_silu)
{
    const int i4 = blockIdx.x * 256 + threadIdx.x;
    const int base = i4 * 4;
    const int c = base >> 13;
    const int group = c >> 4;

    __shared__ float smu, srstd;
    if (threadIdx.x == 0) {
        float s = 0.f, q = 0.f;
        for (int k = 0; k < 8; k++) {
            s += g_part[(group * 8 + k) * 2 + 0];
            q += g_part[(group * 8 + k) * 2 + 1];
        }
        const float mu = s * (1.f / 131072.f);
        smu = mu;
        srstd = rsqrtf(q * (1.f / 131072.f) - mu * mu + 1e-6f);
    }
    __syncthreads();
    const float mu = smu, rstd = srstd;
    const float sc = scale[c], bi = bias[c];

    float4 v = ((const float4*)in)[i4];
    float r[4] = {v.x, v.y, v.z, v.w};
#pragma unroll
    for (int j = 0; j < 4; j++) {
        float t = (r[j] - mu) * rstd * sc + bi;
        if (do_silu) t = t / (1.f + __expf(-t));
        r[j] = t;
    }
    ((float4*)out)[i4] = make_float4(r[0], r[1], r[2], r[3]);
}

// ---------------------------------------------------------------------------
// Edge-replicate pad: (C, 8, 32, 32) -> (C, 10, 34, 34)
// ---------------------------------------------------------------------------
__global__ void pad_kernel(const float* __restrict__ in, float* __restrict__ out)
{
    int idx = blockIdx.x * blockDim.x + threadIdx.x;
    if (idx >= C_DIM * PADN) return;
    int ci = idx / PADN;
    int r = idx - ci * PADN;
    int tp = r / (HP * WP); r -= tp * (HP * WP);
    int yp = r / WP;
    int xp = r - yp * WP;
    int t = tp - 2; if (t < 0) t = 0;
    int y = yp - 1; if (y < 0) y = 0; if (y > HDIM - 1) y = HDIM - 1;
    int x = xp - 1; if (x < 0) x = 0; if (x > WDIM - 1) x = WDIM - 1;
    out[idx] = in[((ci * TDIM + t) * HDIM + y) * WDIM + x];
}

// ---------------------------------------------------------------------------
// Conv3d 3x3x3 (VALID on padded input) + bias + optional residual.
// f32x2 packed inner loop: acc pairs over adjacent x pixels.
// Block: 64 co x 256 positions; per thread 4co x 8 pixel-pairs.
// ---------------------------------------------------------------------------
__global__ __launch_bounds__(256, 2)
void conv_kernel(const float* __restrict__ P, const float* __restrict__ W,
                 const float* __restrict__ bias, const float* __restrict__ resid,
                 float* __restrict__ out)
{
    const int co0 = blockIdx.x * 64;
    const int t   = blockIdx.y >> 2;
    const int y0  = (blockIdx.y & 3) * 8;
    const int tid = threadIdx.x;
    const int tx  = tid & 15;
    const int ty  = tid >> 4;
    const int row = tx >> 1;
    const int x0  = (tx & 1) * 16;

    __shared__ float sA[8][9][64];
    __shared__ float sB[8][10][35];

    u64 acc2[4][8];
#pragma unroll
    for (int i = 0; i < 4; i++)
#pragma unroll
        for (int p = 0; p < 8; p++) acc2[i][p] = 0ull;

    for (int kt = 0; kt < 3; kt++) {
        const int tplane = (t + kt) * (HP * WP);
        for (int c0 = 0; c0 < C_DIM; c0 += 8) {
            for (int i = tid; i < 8 * 9 * 64; i += 256) {
                int ci = i / 576;
                int r2 = i - ci * 576;
                int kk = r2 >> 6;
                int co = r2 & 63;
                sA[ci][kk][co] =
                    W[(size_t)((co0 + co) * C_DIM + (c0 + ci)) * 27 + kt * 9 + kk];
            }
            for (int i = tid; i < 8 * 10 * 34; i += 256) {
                int ci = i / 340;
                int r2 = i - ci * 340;
                int ry = r2 / 34;
                int xx = r2 - ry * 34;
                sB[ci][ry][xx] =
                    P[(size_t)(c0 + ci) * PADN + tplane + (y0 + ry) * WP + xx];
            }
            __syncthreads();

            for (int ci = 0; ci < 8; ci++) {
#pragma unroll
                for (int ky = 0; ky < 3; ky++) {
                    float b[18];
#pragma unroll
                    for (int j = 0; j < 18; j++) b[j] = sB[ci][row + ky][x0 + j];
#pragma unroll
                    for (int kx = 0; kx < 3; kx++) {
                        u64 bp[8];
#pragma unroll
                        for (int p = 0; p < 8; p++)
                            bp[p] = pk2(b[2 * p + kx], b[2 * p + kx + 1]);
#pragma unroll
                        for (int co = 0; co < 4; co++) {
                            const u64 a2 = dup2(sA[ci][ky * 3 + kx][ty * 4 + co]);
#pragma unroll
                            for (int p = 0; p < 8; p++)
                                fma2(acc2[co][p], a2, bp[p]);
                        }
                    }
                }
            }
            __syncthreads();
        }
    }

    // ---- epilogue: bias + optional residual ----
    const int n_base = t * 1024 + (y0 + row) * 32 + x0;
#pragma unroll
    for (int i = 0; i < 4; i++) {
        const int co = co0 + ty * 4 + i;
        const float bb = bias[co];
        const size_t obase = (size_t)co * SPATIAL + n_base;
#pragma unroll
        for (int p = 0; p < 8; p++) {
            float2 f = upk2(acc2[i][p]);
            float v0 = f.x + bb;
            float v1 = f.y + bb;
            if (resid) {
                v0 += resid[obase + 2 * p];
                v1 += resid[obase + 2 * p + 1];
            }
            out[obase + 2 * p]     = v0;
            out[obase + 2 * p + 1] = v1;
        }
    }
}

// ---------------------------------------------------------------------------
// High-performance SGEMM: 128x128x16 tiles, double-buffered smem,
// 8x8 microtile computed as 8x4 packed f32x2 pairs.
// TA=0: A row-major (m,k).  TA=1: A is (k,m).
// TB=0: B (k,n).            TB=1: B is (n,k).
// C row-major.  MODE 0: plain. 1: K causal-clipped. 2: skip masked tile.
// ---------------------------------------------------------------------------
template<int TA, int TB, int MODE>
__global__ __launch_bounds__(256, 2)
void gemm128_kernel(const float* __restrict__ A, const float* __restrict__ B,
                    float* __restrict__ C,
                    int K, int lda, int ldb, int ldc,
                    float alpha,
                    const float* __restrict__ biasM, const float* __restrict__ biasN,
                    const float* __restrict__ resid)
{
    const int n0 = blockIdx.x * 128;
    const int m0 = blockIdx.y * 128;
    if (MODE == 2 && ((n0 >> 10) > (m0 >> 10))) return;
    int Keff = K;
    if (MODE == 1) {
        const int lim = ((m0 >> 10) + 1) << 10;
        if (lim < Keff) Keff = lim;
    }

    __shared__ float sA[2][16][132];
    __shared__ float sB[2][16][132];

    const int tid = threadIdx.x;
    const int lrow = tid >> 2;          // 0..63  (TA==0 / TB==1 row)
    const int lkq  = tid & 3;           // float4 slot along k
    const int lkk  = tid >> 5;          // 0..7   (TA==1 / TB==0 k row)
    const int lmq  = tid & 31;          // float4 slot along m/n

    const int ctx = tid & 15;           // n
    const int cty = tid >> 4;           // m
    const int mt = cty * 8;
    const int nt = ctx * 8;

    u64 acc2[8][4];
#pragma unroll
    for (int i = 0; i < 8; i++)
#pragma unroll
        for (int j = 0; j < 4; j++) acc2[i][j] = 0ull;

    const int nk = Keff >> 4;

    // ---- load tile 0 directly ----
    {
        const int k0 = 0;
        float4 a0, a1, b0, b1;
        if (TA == 0) {
            a0 = *(const float4*)&A[(size_t)(m0 + lrow)      * lda + k0 + lkq * 4];
            a1 = *(const float4*)&A[(size_t)(m0 + lrow + 64) * lda + k0 + lkq * 4];
        } else {
            a0 = *(const float4*)&A[(size_t)(k0 + lkk)     * lda + m0 + lmq * 4];
            a1 = *(const float4*)&A[(size_t)(k0 + lkk + 8) * lda + m0 + lmq * 4];
        }
        if (TB == 0) {
            b0 = *(const float4*)&B[(size_t)(k0 + lkk)     * ldb + n0 + lmq * 4];
            b1 = *(const float4*)&B[(size_t)(k0 + lkk + 8) * ldb + n0 + lmq * 4];
        } else {
            b0 = *(const float4*)&B[(size_t)(n0 + lrow)      * ldb + k0 + lkq * 4];
            b1 = *(const float4*)&B[(size_t)(n0 + lrow + 64) * ldb + k0 + lkq * 4];
        }
        if (TA == 0) {
            sA[0][lkq*4+0][lrow] = a0.x; sA[0][lkq*4+1][lrow] = a0.y;
            sA[0][lkq*4+2][lrow] = a0.z; sA[0][lkq*4+3][lrow] = a0.w;
            sA[0][lkq*4+0][lrow+64] = a1.x; sA[0][lkq*4+1][lrow+64] = a1.y;
            sA[0][lkq*4+2][lrow+64] = a1.z; sA[0][lkq*4+3][lrow+64] = a1.w;
        } else {
            *(float4*)&sA[0][lkk][lmq*4]   = a0;
            *(float4*)&sA[0][lkk+8][lmq*4] = a1;
        }
        if (TB == 0) {
            *(float4*)&sB[0][lkk][lmq*4]   = b0;
            *(float4*)&sB[0][lkk+8][lmq*4] = b1;
        } else {
            sB[0][lkq*4+0][lrow] = b0.x; sB[0][lkq*4+1][lrow] = b0.y;
            sB[0][lkq*4+2][lrow] = b0.z; sB[0][lkq*4+3][lrow] = b0.w;
            sB[0][lkq*4+0][lrow+64] = b1.x; sB[0][lkq*4+1][lrow+64] = b1.y;
            sB[0][lkq*4+2][lrow+64] = b1.z; sB[0][lkq*4+3][lrow+64] = b1.w;
        }
    }
    __syncthreads();

    int buf = 0;
    for (int kt = 0; kt < nk; kt++) {
        const int nxt = kt + 1;
        float4 pa0, pa1, pb0, pb1;
        if (nxt < nk) {
            const int k0 = nxt << 4;
            if (TA == 0) {
                pa0 = *(const float4*)&A[(size_t)(m0 + lrow)      * lda + k0 + lkq * 4];
                pa1 = *(const float4*)&A[(size_t)(m0 + lrow + 64) * lda + k0 + lkq * 4];
            } else {
                pa0 = *(const float4*)&A[(size_t)(k0 + lkk)     * lda + m0 + lmq * 4];
                pa1 = *(const float4*)&A[(size_t)(k0 + lkk + 8) * lda + m0 + lmq * 4];
            }
            if (TB == 0) {
                pb0 = *(const float4*)&B[(size_t)(k0 + lkk)     * ldb + n0 + lmq * 4];
                pb1 = *(const float4*)&B[(size_t)(k0 + lkk + 8) * ldb + n0 + lmq * 4];
            } else {
                pb0 = *(const float4*)&B[(size_t)(n0 + lrow)      * ldb + k0 + lkq * 4];
                pb1 = *(const float4*)&B[(size_t)(n0 + lrow + 64) * ldb + k0 + lkq * 4];
            }
        }

        // ---- compute on smem[buf]: packed f32x2 ----
#pragma unroll
        for (int k = 0; k < 16; k++) {
            float4 av0 = *(const float4*)&sA[buf][k][mt];
            float4 av1 = *(const float4*)&sA[buf][k][mt + 4];
            float4 bv0 = *(const float4*)&sB[buf][k][nt];
            float4 bv1 = *(const float4*)&sB[buf][k][nt + 4];
            u64 b2[4];
            b2[0] = pk2(bv0.x, bv0.y);
            b2[1] = pk2(bv0.z, bv0.w);
            b2[2] = pk2(bv1.x, bv1.y);
            b2[3] = pk2(bv1.z, bv1.w);
            u64 a2[8];
            a2[0] = dup2(av0.x); a2[1] = dup2(av0.y);
            a2[2] = dup2(av0.z); a2[3] = dup2(av0.w);
            a2[4] = dup2(av1.x); a2[5] = dup2(av1.y);
            a2[6] = dup2(av1.z); a2[7] = dup2(av1.w);
#pragma unroll
            for (int i = 0; i < 8; i++)
#pragma unroll
                for (int j = 0; j < 4; j++)
                    fma2(acc2[i][j], a2[i], b2[j]);
        }

        if (nxt < nk) {
            const int nb = buf ^ 1;
            if (TA == 0) {
                sA[nb][lkq*4+0][lrow] = pa0.x; sA[nb][lkq*4+1][lrow] = pa0.y;
                sA[nb][lkq*4+2][lrow] = pa0.z; sA[nb][lkq*4+3][lrow] = pa0.w;
                sA[nb][lkq*4+0][lrow+64] = pa1.x; sA[nb][lkq*4+1][lrow+64] = pa1.y;
                sA[nb][lkq*4+2][lrow+64] = pa1.z; sA[nb][lkq*4+3][lrow+64] = pa1.w;
            } else {
                *(float4*)&sA[nb][lkk][lmq*4]   = pa0;
                *(float4*)&sA[nb][lkk+8][lmq*4] = pa1;
            }
            if (TB == 0) {
                *(float4*)&sB[nb][lkk][lmq*4]   = pb0;
                *(float4*)&sB[nb][lkk+8][lmq*4] = pb1;
            } else {
                sB[nb][lkq*4+0][lrow] = pb0.x; sB[nb][lkq*4+1][lrow] = pb0.y;
                sB[nb][lkq*4+2][lrow] = pb0.z; sB[nb][lkq*4+3][lrow] = pb0.w;
                sB[nb][lkq*4+0][lrow+64] = pb1.x; sB[nb][lkq*4+1][lrow+64] = pb1.y;
                sB[nb][lkq*4+2][lrow+64] = pb1.z; sB[nb][lkq*4+3][lrow+64] = pb1.w;
            }
            __syncthreads();
        }
        buf ^= 1;
    }

    // ---- epilogue ----
#pragma unroll
    for (int i = 0; i < 8; i++) {
        const int m = m0 + mt + i;
        const float bm = biasM ? biasM[m] : 0.f;
        const size_t crow = (size_t)m * ldc + n0 + nt;
#pragma unroll
        for (int jj = 0; jj < 2; jj++) {
            float2 f0 = upk2(acc2[i][jj * 2 + 0]);
            float2 f1 = upk2(acc2[i][jj * 2 + 1]);
            float4 v;
            v.x = f0.x * alpha + bm;
            v.y = f0.y * alpha + bm;
            v.z = f1.x * alpha + bm;
            v.w = f1.y * alpha + bm;
            if (biasN) {
                const float4 bn = *(const float4*)&biasN[n0 + nt + jj*4];
                v.x += bn.x; v.y += bn.y; v.z += bn.z; v.w += bn.w;
            }
            if (resid) {
                const float4 rv = *(const float4*)&resid[crow + jj*4];
                v.x += rv.x; v.y += rv.y; v.z += rv.z; v.w += rv.w;
            }
            *(float4*)&C[crow + jj*4] = v;
        }
    }
}

// ---------------------------------------------------------------------------
// Row softmax over causal prefix L = ((q>>10)+1)*1024, in place on g_scores.
// ---------------------------------------------------------------------------
__global__ void softmax_kernel(float* __restrict__ S)
{
    const int q = blockIdx.x;
    const int L = ((q >> 10) + 1) << 10;
    float* row = S + (size_t)q * SPATIAL;
    __shared__ float red[32];
    const int wid = threadIdx.x >> 5, lid = threadIdx.x & 31;
    const int nw = blockDim.x >> 5;

    float mx = -1e30f;
    for (int i = threadIdx.x; i < L; i += blockDim.x) mx = fmaxf(mx, row[i]);
    for (int o = 16; o; o >>= 1) mx = fmaxf(mx, __shfl_xor_sync(0xffffffffu, mx, o));
    if (lid == 0) red[wid] = mx;
    __syncthreads();
    if (wid == 0) {
        float v = (lid < nw) ? red[lid] : -1e30f;
        for (int o = 16; o; o >>= 1) v = fmaxf(v, __shfl_xor_sync(0xffffffffu, v, o));
        if (lid == 0) red[0] = v;
    }
    __syncthreads();
    mx = red[0];
    __syncthreads();

    float sum = 0.f;
    for (int i = threadIdx.x; i < L; i += blockDim.x) {
        float e = __expf(row[i] - mx);
        row[i] = e;
        sum += e;
    }
    for (int o = 16; o; o >>= 1) sum += __shfl_xor_sync(0xffffffffu, sum, o);
    if (lid == 0) red[wid] = sum;
    __syncthreads();
    if (wid == 0) {
        float v = (lid < nw) ? red[lid] : 0.f;
        for (int o = 16; o; o >>= 1) v += __shfl_xor_sync(0xffffffffu, v, o);
        if (lid == 0) red[0] = v;
    }
    __syncthreads();
    const float inv = 1.f / red[0];
    for (int i = threadIdx.x; i < L; i += blockDim.x) row[i] *= inv;
}

// ---------------------------------------------------------------------------
// Host orchestration
// ---------------------------------------------------------------------------
static inline void run_gn(const float* in, float* out, const float* s, const float* b, int silu)
{
    gn_stats_kernel<<<256, 256>>>(in);
    gn_apply_kernel<<<4096, 256>>>(in, out, s, b, silu);
}

extern "C" void kernel_launch(void* const* d_in, const int* in_sizes, int n_in,
                              void* d_out, int out_size)
{
    (void)in_sizes; (void)n_in; (void)out_size;

    const float* x      = (const float*)d_in[0];
    const float* r0_n1s = (const float*)d_in[1];
    const float* r0_n1b = (const float*)d_in[2];
    const float* r0_w1  = (const float*)d_in[3];
    const float* r0_b1  = (const float*)d_in[4];
    const float* r0_n2s = (const float*)d_in[5];
    const float* r0_n2b = (const float*)d_in[6];
    const float* r0_w2  = (const float*)d_in[7];
    const float* r0_b2  = (const float*)d_in[8];
    const float* r1_n1s = (const float*)d_in[9];
    const float* r1_n1b = (const float*)d_in[10];
    const float* r1_w1  = (const float*)d_in[11];
    const float* r1_b1  = (const float*)d_in[12];
    const float* r1_n2s = (const float*)d_in[13];
    const float* r1_n2b = (const float*)d_in[14];
    const float* r1_w2  = (const float*)d_in[15];
    const float* r1_b2  = (const float*)d_in[16];
    const float* a_gns  = (const float*)d_in[17];
    const float* a_gnb  = (const float*)d_in[18];
    const float* a_wq   = (const float*)d_in[19];
    const float* a_bq   = (const float*)d_in[20];
    const float* a_wk   = (const float*)d_in[21];
    const float* a_bk   = (const float*)d_in[22];
    const float* a_wv   = (const float*)d_in[23];
    const float* a_bv   = (const float*)d_in[24];
    const float* a_wo   = (const float*)d_in[25];
    const float* a_bo   = (const float*)d_in[26];
    float* out = (float*)d_out;

    float *bufA, *bufB, *padb, *qb, *kb, *vb, *aob, *sb;
    cudaGetSymbolAddress((void**)&bufA, g_bufA);
    cudaGetSymbolAddress((void**)&bufB, g_bufB);
    cudaGetSymbolAddress((void**)&padb, g_padbuf);
    cudaGetSymbolAddress((void**)&qb,   g_q);
    cudaGetSymbolAddress((void**)&kb,   g_k);
    cudaGetSymbolAddress((void**)&vb,   g_v);
    cudaGetSymbolAddress((void**)&aob,  g_ao);
    cudaGetSymbolAddress((void**)&sb,   g_scores);

    const int padGrid = (C_DIM * PADN + 255) / 256;
    const dim3 convGrid(8, 32);
    const float att_scale = 0.04419417382415922f;   // 512^-0.5

    // ---------------- resnet block 0 ----------------
    run_gn(x, bufA, r0_n1s, r0_n1b, 1);
    pad_kernel<<<padGrid, 256>>>(bufA, padb);
    conv_kernel<<<convGrid, 256>>>(padb, r0_w1, r0_b1, nullptr, bufB);
    run_gn(bufB, bufA, r0_n2s, r0_n2b, 1);
    pad_kernel<<<padGrid, 256>>>(bufA, padb);
    conv_kernel<<<convGrid, 256>>>(padb, r0_w2, r0_b2, x, bufB);   // bufB = h0

    // ---------------- attention ----------------
    run_gn(bufB, bufA, a_gns, a_gnb, 0);                           // bufA = xn (c,s)
    // q/k/v: [s, o] = sum_c xn[c,s] * w[o,c] + b[o]
    {
        dim3 g(C_DIM / 128, SPATIAL / 128);
        gemm128_kernel<1, 1, 0><<<g, 256>>>(bufA, a_wq, qb, C_DIM, SPATIAL, C_DIM, C_DIM,
                                            1.f, nullptr, a_bq, nullptr);
        gemm128_kernel<1, 1, 0><<<g, 256>>>(bufA, a_wk, kb, C_DIM, SPATIAL, C_DIM, C_DIM,
                                            1.f, nullptr, a_bk, nullptr);
        gemm128_kernel<1, 1, 0><<<g, 256>>>(bufA, a_wv, vb, C_DIM, SPATIAL, C_DIM, C_DIM,
                                            1.f, nullptr, a_bv, nullptr);
    }
    // scores[q,k] = scale * sum_d Q[q,d] K[k,d]   (skip masked tiles)
    {
        dim3 g(SPATIAL / 128, SPATIAL / 128);
        gemm128_kernel<0, 1, 2><<<g, 256>>>(qb, kb, sb, C_DIM, C_DIM, C_DIM, SPATIAL,
                                            att_scale, nullptr, nullptr, nullptr);
    }
    softmax_kernel<<<SPATIAL, 256>>>(sb);
    // AO[q,d] = sum_k P[q,k] V[k,d]   (K limited to causal prefix)
    {
        dim3 g(C_DIM / 128, SPATIAL / 128);
        gemm128_kernel<0, 0, 1><<<g, 256>>>(sb, vb, aob, SPATIAL, SPATIAL, C_DIM, C_DIM,
                                            1.f, nullptr, nullptr, nullptr);
    }
    // h1[c,s] = h0[c,s] + bo[c] + sum_d AO[s,d] * wo[c,d]
    {
        dim3 g(SPATIAL / 128, C_DIM / 128);
        gemm128_kernel<0, 1, 0><<<g, 256>>>(a_wo, aob, bufA, C_DIM, C_DIM, C_DIM, SPATIAL,
                                            1.f, a_bo, nullptr, bufB);   // bufA = h1
    }

    // ---------------- resnet block 1 ----------------
    run_gn(bufA, bufB, r1_n1s, r1_n1b, 1);
    pad_kernel<<<padGrid, 256>>>(bufB, padb);
    conv_kernel<<<convGrid, 256>>>(padb, r1_w1, r1_b1, nullptr, bufB);
    run_gn(bufB, qb, r1_n2s, r1_n2b, 1);
    pad_kernel<<<padGrid, 256>>>(qb, padb);
    conv_kernel<<<convGrid, 256>>>(padb, r1_w2, r1_b2, bufA, out); // out = h1 + conv
}

// round 12
// speedup vs baseline: 1.6144x; 1.5406x over previous
#include <cuda_runtime.h>
#include <cuda_bf16.h>
#include <mma.h>
#include <math.h>

using namespace nvcuda;

// ---------------------------------------------------------------------------
// Problem constants
// ---------------------------------------------------------------------------
#define C_DIM   512
#define TDIM    8
#define HDIM    32
#define WDIM    32
#define SPATIAL 8192            // T*H*W
#define GROUPS  32
#define TP      10              // padded T (2,0)
#define HP      34              // padded H (1,1)
#define WP      34              // padded W (1,1)
#define PADN    (TP*HP*WP)      // 11560
#define NTAPS   27
#define CI_CHUNK 64
#define LDAB    72              // smem row stride (bf16 elems), 144B (conflict-shifting)

typedef unsigned long long u64;

// ---------------------------------------------------------------------------
// Packed f32x2 helpers (GEMM path, proven in R7)
// ---------------------------------------------------------------------------
__device__ __forceinline__ u64 pk2(float lo, float hi) {
    u64 r; asm("mov.b64 %0, {%1, %2};" : "=l"(r) : "f"(lo), "f"(hi)); return r;
}
__device__ __forceinline__ u64 dup2(float v) {
    u64 r; asm("mov.b64 %0, {%1, %1};" : "=l"(r) : "f"(v)); return r;
}
__device__ __forceinline__ void fma2(u64& d, u64 a, u64 b) {
    asm("fma.rn.f32x2 %0, %1, %2, %0;" : "+l"(d) : "l"(a), "l"(b));
}
__device__ __forceinline__ float2 upk2(u64 v) {
    float2 f; asm("mov.b64 {%0, %1}, %2;" : "=f"(f.x), "=f"(f.y) : "l"(v)); return f;
}

// ---------------------------------------------------------------------------
// Scratch (device globals; no runtime allocation allowed)
// ---------------------------------------------------------------------------
__device__ float g_bufA[C_DIM * SPATIAL];
__device__ float g_bufB[C_DIM * SPATIAL];
__device__ float g_q[SPATIAL * C_DIM];
__device__ float g_k[SPATIAL * C_DIM];
__device__ float g_v[SPATIAL * C_DIM];
__device__ float g_ao[SPATIAL * C_DIM];
__device__ float g_part[256 * 2];                          // GN partials
__device__ float g_scores[(size_t)SPATIAL * SPATIAL];      // 256 MB
// conv bf16 split operands
__device__ __nv_bfloat16 g_phiT[(size_t)PADN * C_DIM];     // P^T hi  [sp][ci]
__device__ __nv_bfloat16 g_ploT[(size_t)PADN * C_DIM];     // P^T lo
__device__ __nv_bfloat16 g_wtHi[(size_t)NTAPS * C_DIM * C_DIM]; // [tap][co][ci]
__device__ __nv_bfloat16 g_wtLo[(size_t)NTAPS * C_DIM * C_DIM];

// ---------------------------------------------------------------------------
// GroupNorm pass 1 (unchanged, proven)
// ---------------------------------------------------------------------------
__global__ void gn_stats_kernel(const float* __restrict__ in)
{
    const int blk = blockIdx.x;
    const float4* p = (const float4*)(in + (size_t)blk * 16384);
    float sum = 0.f, sq = 0.f;
    for (int i = threadIdx.x; i < 4096; i += 256) {
        float4 v = p[i];
        sum += v.x + v.y + v.z + v.w;
        sq  += v.x*v.x + v.y*v.y + v.z*v.z + v.w*v.w;
    }
    __shared__ float ss[8], sg[8];
    for (int o = 16; o; o >>= 1) {
        sum += __shfl_xor_sync(0xffffffffu, sum, o);
        sq  += __shfl_xor_sync(0xffffffffu, sq,  o);
    }
    const int wid = threadIdx.x >> 5, lid = threadIdx.x & 31;
    if (lid == 0) { ss[wid] = sum; sg[wid] = sq; }
    __syncthreads();
    if (threadIdx.x == 0) {
        float a = 0.f, b = 0.f;
        for (int w = 0; w < 8; w++) { a += ss[w]; b += sg[w]; }
        g_part[blk * 2 + 0] = a;
        g_part[blk * 2 + 1] = b;
    }
}

// ---------------------------------------------------------------------------
// GroupNorm pass 2 (unchanged, proven)
// ---------------------------------------------------------------------------
__global__ void gn_apply_kernel(const float* __restrict__ in, float* __restrict__ out,
                                const float* __restrict__ scale, const float* __restrict__ bias,
                                int do_silu)
{
    const int i4 = blockIdx.x * 256 + threadIdx.x;
    const int base = i4 * 4;
    const int c = base >> 13;
    const int group = c >> 4;

    __shared__ float smu, srstd;
    if (threadIdx.x == 0) {
        float s = 0.f, q = 0.f;
        for (int k = 0; k < 8; k++) {
            s += g_part[(group * 8 + k) * 2 + 0];
            q += g_part[(group * 8 + k) * 2 + 1];
        }
        const float mu = s * (1.f / 131072.f);
        smu = mu;
        srstd = rsqrtf(q * (1.f / 131072.f) - mu * mu + 1e-6f);
    }
    __syncthreads();
    const float mu = smu, rstd = srstd;
    const float sc = scale[c], bi = bias[c];

    float4 v = ((const float4*)in)[i4];
    float r[4] = {v.x, v.y, v.z, v.w};
#pragma unroll
    for (int j = 0; j < 4; j++) {
        float t = (r[j] - mu) * rstd * sc + bi;
        if (do_silu) t = t / (1.f + __expf(-t));
        r[j] = t;
    }
    ((float4*)out)[i4] = make_float4(r[0], r[1], r[2], r[3]);
}

// ---------------------------------------------------------------------------
// pad + transpose + bf16-split: in[ci][8,32,32] -> PhiT/PloT [sp][ci] bf16
// ---------------------------------------------------------------------------
__global__ void pad_split_kernel(const float* __restrict__ in)
{
    const size_t id = (size_t)blockIdx.x * 256 + threadIdx.x;
    if (id >= (size_t)PADN * C_DIM) return;
    const int ci = (int)(id & 511);
    int sp = (int)(id >> 9);
    int tp = sp / (HP * WP); int r = sp - tp * (HP * WP);
    int yp = r / WP; int xp = r - yp * WP;
    int t = tp - 2; if (t < 0) t = 0;
    int y = yp - 1; if (y < 0) y = 0; if (y > HDIM - 1) y = HDIM - 1;
    int x = xp - 1; if (x < 0) x = 0; if (x > WDIM - 1) x = WDIM - 1;
    float v = in[(size_t)ci * SPATIAL + t * 1024 + y * 32 + x];
    __nv_bfloat16 hi = __float2bfloat16(v);
    __nv_bfloat16 lo = __float2bfloat16(v - __bfloat162float(hi));
    g_phiT[id] = hi;
    g_ploT[id] = lo;
}

// ---------------------------------------------------------------------------
// Weight transpose + bf16-split: W[co][ci][27] fp32 -> WtHi/WtLo [tap][co][ci]
// ---------------------------------------------------------------------------
__global__ void wsplit_kernel(const float* __restrict__ W)
{
    const int id = blockIdx.x * 256 + threadIdx.x;   // co*512+ci
    if (id >= C_DIM * C_DIM) return;
    const float* src = W + (size_t)id * NTAPS;
#pragma unroll
    for (int tap = 0; tap < NTAPS; tap++) {
        float v = src[tap];
        __nv_bfloat16 hi = __float2bfloat16(v);
        __nv_bfloat16 lo = __float2bfloat16(v - __bfloat162float(hi));
        const size_t o = (size_t)tap * (C_DIM * C_DIM) + id;
        g_wtHi[o] = hi;
        g_wtLo[o] = lo;
    }
}

// ---------------------------------------------------------------------------
// WMMA conv: D[128co x 128pos] = sum over 27 taps x 8 ci-chunks of the
// 3-term bf16-split product, fp32 accumulators in registers.
// 8 warps: warp tile 64co x 32pos (2 m-warps x 4 n-warps).
// Non-'a' path only: wmma/mma.sync is legal on compute_103.
// ---------------------------------------------------------------------------
#define CONV_SMEM_DYN (4 * 128 * LDAB * 2)    // 73728 B: Ahi, Alo, Bhi, Blo

__global__ __launch_bounds__(256)
void conv_wmma_kernel(const float* __restrict__ bias, const float* __restrict__ resid,
                      float* __restrict__ out)
{
    extern __shared__ char dsm[];
    __nv_bfloat16* sAhi = (__nv_bfloat16*)dsm;
    __nv_bfloat16* sAlo = sAhi + 128 * LDAB;
    __nv_bfloat16* sBhi = sAlo + 128 * LDAB;
    __nv_bfloat16* sBlo = sBhi + 128 * LDAB;
    float* sC = (float*)dsm;                   // epilogue reuse (64 KB < 72 KB)

    const int tid = threadIdx.x;
    const int wid = tid >> 5;
    const int co0 = blockIdx.x * 128;
    const int t0  = blockIdx.y >> 3;
    const int y0  = (blockIdx.y & 7) * 4;
    const int wm  = (wid & 1) * 64;            // warp m offset (co)
    const int wn  = (wid >> 1) * 32;           // warp n offset (pos)

    wmma::fragment<wmma::accumulator, 16, 16, 16, float> acc[4][2];
#pragma unroll
    for (int i = 0; i < 4; i++)
#pragma unroll
        for (int j = 0; j < 2; j++) wmma::fill_fragment(acc[i][j], 0.f);

    // fill task: thread owns one row of one (hi/lo) buffer pair
    const int rowT  = tid & 127;
    const int which = tid >> 7;                 // 0 = hi, 1 = lo
    const __nv_bfloat16* Asrc = which ? g_wtLo : g_wtHi;
    const __nv_bfloat16* Bsrc = which ? g_ploT : g_phiT;
    __nv_bfloat16* Adst = (which ? sAlo : sAhi) + rowT * LDAB;
    __nv_bfloat16* Bdst = (which ? sBlo : sBhi) + rowT * LDAB;
    const int yy = rowT >> 5, xx = rowT & 31;

    for (int tap = 0; tap < NTAPS; tap++) {
        const int kt = tap / 9, rr = tap - kt * 9;
        const int ky = rr / 3,  kx = rr - ky * 3;
        const int spbase = (t0 + kt) * (HP * WP) + (y0 + ky) * WP + kx;
        const size_t aTap = (size_t)tap * (C_DIM * C_DIM) + (size_t)(co0 + rowT) * C_DIM;
        const size_t bRow = (size_t)(spbase + yy * WP + xx) * C_DIM;

        for (int ci0 = 0; ci0 < C_DIM; ci0 += CI_CHUNK) {
            __syncthreads();                    // previous compute done
            const uint4* ag = (const uint4*)(Asrc + aTap + ci0);
            const uint4* bg = (const uint4*)(Bsrc + bRow + ci0);
            uint4* ad = (uint4*)Adst;
            uint4* bd = (uint4*)Bdst;
#pragma unroll
            for (int j = 0; j < 8; j++) ad[j] = ag[j];
#pragma unroll
            for (int j = 0; j < 8; j++) bd[j] = bg[j];
            __syncthreads();                    // tiles visible

            // 3 split terms: AhiBhi + AhiBlo + AloBhi
#pragma unroll
            for (int term = 0; term < 3; term++) {
                const __nv_bfloat16* Ap = (term == 2) ? sAlo : sAhi;
                const __nv_bfloat16* Bp = (term == 1) ? sBlo : sBhi;
#pragma unroll
                for (int kk = 0; kk < 4; kk++) {
                    wmma::fragment<wmma::matrix_a, 16, 16, 16, __nv_bfloat16,
                                   wmma::row_major> a_frag[4];
                    wmma::fragment<wmma::matrix_b, 16, 16, 16, __nv_bfloat16,
                                   wmma::col_major> b_frag[2];
#pragma unroll
                    for (int i = 0; i < 4; i++)
                        wmma::load_matrix_sync(a_frag[i],
                            Ap + (wm + i * 16) * LDAB + kk * 16, LDAB);
#pragma unroll
                    for (int j = 0; j < 2; j++)
                        wmma::load_matrix_sync(b_frag[j],
                            Bp + (wn + j * 16) * LDAB + kk * 16, LDAB);
#pragma unroll
                    for (int i = 0; i < 4; i++)
#pragma unroll
                        for (int j = 0; j < 2; j++)
                            wmma::mma_sync(acc[i][j], a_frag[i], b_frag[j], acc[i][j]);
                }
            }
        }
    }

    // ---- epilogue: frags -> smem -> gmem with bias + optional residual ----
    __syncthreads();
#pragma unroll
    for (int i = 0; i < 4; i++)
#pragma unroll
        for (int j = 0; j < 2; j++)
            wmma::store_matrix_sync(sC + (wm + i * 16) * 128 + wn + j * 16,
                                    acc[i][j], 128, wmma::mem_row_major);
    __syncthreads();

    for (int idx = tid; idx < 128 * 32; idx += 256) {
        const int row = idx >> 5;               // local co
        const int c4  = idx & 31;               // float4 column
        float4 v = ((const float4*)(sC + row * 128))[c4];
        const int co = co0 + row;
        const float bb = bias[co];
        v.x += bb; v.y += bb; v.z += bb; v.w += bb;
        const size_t o = (size_t)co * SPATIAL + t0 * 1024 + y0 * 32 + c4 * 4;
        if (resid) {
            const float4 rv = *(const float4*)&resid[o];
            v.x += rv.x; v.y += rv.y; v.z += rv.z; v.w += rv.w;
        }
        *(float4*)&out[o] = v;
    }
}

// ---------------------------------------------------------------------------
// SGEMM 128x128x16, double-buffered, f32x2 microtile (unchanged, proven R7)
// ---------------------------------------------------------------------------
template<int TA, int TB, int MODE>
__global__ __launch_bounds__(256, 2)
void gemm128_kernel(const float* __restrict__ A, const float* __restrict__ B,
                    float* __restrict__ C,
                    int K, int lda, int ldb, int ldc,
                    float alpha,
                    const float* __restrict__ biasM, const float* __restrict__ biasN,
                    const float* __restrict__ resid)
{
    const int n0 = blockIdx.x * 128;
    const int m0 = blockIdx.y * 128;
    if (MODE == 2 && ((n0 >> 10) > (m0 >> 10))) return;
    int Keff = K;
    if (MODE == 1) {
        const int lim = ((m0 >> 10) + 1) << 10;
        if (lim < Keff) Keff = lim;
    }

    __shared__ float sA[2][16][132];
    __shared__ float sB[2][16][132];

    const int tid = threadIdx.x;
    const int lrow = tid >> 2;
    const int lkq  = tid & 3;
    const int lkk  = tid >> 5;
    const int lmq  = tid & 31;

    const int ctx = tid & 15;
    const int cty = tid >> 4;
    const int mt = cty * 8;
    const int nt = ctx * 8;

    u64 acc2[8][4];
#pragma unroll
    for (int i = 0; i < 8; i++)
#pragma unroll
        for (int j = 0; j < 4; j++) acc2[i][j] = 0ull;

    const int nk = Keff >> 4;

    {
        const int k0 = 0;
        float4 a0, a1, b0, b1;
        if (TA == 0) {
            a0 = *(const float4*)&A[(size_t)(m0 + lrow)      * lda + k0 + lkq * 4];
            a1 = *(const float4*)&A[(size_t)(m0 + lrow + 64) * lda + k0 + lkq * 4];
        } else {
            a0 = *(const float4*)&A[(size_t)(k0 + lkk)     * lda + m0 + lmq * 4];
            a1 = *(const float4*)&A[(size_t)(k0 + lkk + 8) * lda + m0 + lmq * 4];
        }
        if (TB == 0) {
            b0 = *(const float4*)&B[(size_t)(k0 + lkk)     * ldb + n0 + lmq * 4];
            b1 = *(const float4*)&B[(size_t)(k0 + lkk + 8) * ldb + n0 + lmq * 4];
        } else {
            b0 = *(const float4*)&B[(size_t)(n0 + lrow)      * ldb + k0 + lkq * 4];
            b1 = *(const float4*)&B[(size_t)(n0 + lrow + 64) * ldb + k0 + lkq * 4];
        }
        if (TA == 0) {
            sA[0][lkq*4+0][lrow] = a0.x; sA[0][lkq*4+1][lrow] = a0.y;
            sA[0][lkq*4+2][lrow] = a0.z; sA[0][lkq*4+3][lrow] = a0.w;
            sA[0][lkq*4+0][lrow+64] = a1.x; sA[0][lkq*4+1][lrow+64] = a1.y;
            sA[0][lkq*4+2][lrow+64] = a1.z; sA[0][lkq*4+3][lrow+64] = a1.w;
        } else {
            *(float4*)&sA[0][lkk][lmq*4]   = a0;
            *(float4*)&sA[0][lkk+8][lmq*4] = a1;
        }
        if (TB == 0) {
            *(float4*)&sB[0][lkk][lmq*4]   = b0;
            *(float4*)&sB[0][lkk+8][lmq*4] = b1;
        } else {
            sB[0][lkq*4+0][lrow] = b0.x; sB[0][lkq*4+1][lrow] = b0.y;
            sB[0][lkq*4+2][lrow] = b0.z; sB[0][lkq*4+3][lrow] = b0.w;
            sB[0][lkq*4+0][lrow+64] = b1.x; sB[0][lkq*4+1][lrow+64] = b1.y;
            sB[0][lkq*4+2][lrow+64] = b1.z; sB[0][lkq*4+3][lrow+64] = b1.w;
        }
    }
    __syncthreads();

    int buf = 0;
    for (int kt = 0; kt < nk; kt++) {
        const int nxt = kt + 1;
        float4 pa0, pa1, pb0, pb1;
        if (nxt < nk) {
            const int k0 = nxt << 4;
            if (TA == 0) {
                pa0 = *(const float4*)&A[(size_t)(m0 + lrow)      * lda + k0 + lkq * 4];
                pa1 = *(const float4*)&A[(size_t)(m0 + lrow + 64) * lda + k0 + lkq * 4];
            } else {
                pa0 = *(const float4*)&A[(size_t)(k0 + lkk)     * lda + m0 + lmq * 4];
                pa1 = *(const float4*)&A[(size_t)(k0 + lkk + 8) * lda + m0 + lmq * 4];
            }
            if (TB == 0) {
                pb0 = *(const float4*)&B[(size_t)(k0 + lkk)     * ldb + n0 + lmq * 4];
                pb1 = *(const float4*)&B[(size_t)(k0 + lkk + 8) * ldb + n0 + lmq * 4];
            } else {
                pb0 = *(const float4*)&B[(size_t)(n0 + lrow)      * ldb + k0 + lkq * 4];
                pb1 = *(const float4*)&B[(size_t)(n0 + lrow + 64) * ldb + k0 + lkq * 4];
            }
        }

#pragma unroll
        for (int k = 0; k < 16; k++) {
            float4 av0 = *(const float4*)&sA[buf][k][mt];
            float4 av1 = *(const float4*)&sA[buf][k][mt + 4];
            float4 bv0 = *(const float4*)&sB[buf][k][nt];
            float4 bv1 = *(const float4*)&sB[buf][k][nt + 4];
            u64 b2[4];
            b2[0] = pk2(bv0.x, bv0.y);
            b2[1] = pk2(bv0.z, bv0.w);
            b2[2] = pk2(bv1.x, bv1.y);
            b2[3] = pk2(bv1.z, bv1.w);
            u64 a2[8];
            a2[0] = dup2(av0.x); a2[1] = dup2(av0.y);
            a2[2] = dup2(av0.z); a2[3] = dup2(av0.w);
            a2[4] = dup2(av1.x); a2[5] = dup2(av1.y);
            a2[6] = dup2(av1.z); a2[7] = dup2(av1.w);
#pragma unroll
            for (int i = 0; i < 8; i++)
#pragma unroll
                for (int j = 0; j < 4; j++)
                    fma2(acc2[i][j], a2[i], b2[j]);
        }

        if (nxt < nk) {
            const int nb = buf ^ 1;
            if (TA == 0) {
                sA[nb][lkq*4+0][lrow] = pa0.x; sA[nb][lkq*4+1][lrow] = pa0.y;
                sA[nb][lkq*4+2][lrow] = pa0.z; sA[nb][lkq*4+3][lrow] = pa0.w;
                sA[nb][lkq*4+0][lrow+64] = pa1.x; sA[nb][lkq*4+1][lrow+64] = pa1.y;
                sA[nb][lkq*4+2][lrow+64] = pa1.z; sA[nb][lkq*4+3][lrow+64] = pa1.w;
            } else {
                *(float4*)&sA[nb][lkk][lmq*4]   = pa0;
                *(float4*)&sA[nb][lkk+8][lmq*4] = pa1;
            }
            if (TB == 0) {
                *(float4*)&sB[nb][lkk][lmq*4]   = pb0;
                *(float4*)&sB[nb][lkk+8][lmq*4] = pb1;
            } else {
                sB[nb][lkq*4+0][lrow] = pb0.x; sB[nb][lkq*4+1][lrow] = pb0.y;
                sB[nb][lkq*4+2][lrow] = pb0.z; sB[nb][lkq*4+3][lrow] = pb0.w;
                sB[nb][lkq*4+0][lrow+64] = pb1.x; sB[nb][lkq*4+1][lrow+64] = pb1.y;
                sB[nb][lkq*4+2][lrow+64] = pb1.z; sB[nb][lkq*4+3][lrow+64] = pb1.w;
            }
            __syncthreads();
        }
        buf ^= 1;
    }

#pragma unroll
    for (int i = 0; i < 8; i++) {
        const int m = m0 + mt + i;
        const float bm = biasM ? biasM[m] : 0.f;
        const size_t crow = (size_t)m * ldc + n0 + nt;
#pragma unroll
        for (int jj = 0; jj < 2; jj++) {
            float2 f0 = upk2(acc2[i][jj * 2 + 0]);
            float2 f1 = upk2(acc2[i][jj * 2 + 1]);
            float4 v;
            v.x = f0.x * alpha + bm;
            v.y = f0.y * alpha + bm;
            v.z = f1.x * alpha + bm;
            v.w = f1.y * alpha + bm;
            if (biasN) {
                const float4 bn = *(const float4*)&biasN[n0 + nt + jj*4];
                v.x += bn.x; v.y += bn.y; v.z += bn.z; v.w += bn.w;
            }
            if (resid) {
                const float4 rv = *(const float4*)&resid[crow + jj*4];
                v.x += rv.x; v.y += rv.y; v.z += rv.z; v.w += rv.w;
            }
            *(float4*)&C[crow + jj*4] = v;
        }
    }
}

// ---------------------------------------------------------------------------
// Row softmax over causal prefix (unchanged, proven)
// ---------------------------------------------------------------------------
__global__ void softmax_kernel(float* __restrict__ S)
{
    const int q = blockIdx.x;
    const int L = ((q >> 10) + 1) << 10;
    float* row = S + (size_t)q * SPATIAL;
    __shared__ float red[32];
    const int wid = threadIdx.x >> 5, lid = threadIdx.x & 31;
    const int nw = blockDim.x >> 5;

    float mx = -1e30f;
    for (int i = threadIdx.x; i < L; i += blockDim.x) mx = fmaxf(mx, row[i]);
    for (int o = 16; o; o >>= 1) mx = fmaxf(mx, __shfl_xor_sync(0xffffffffu, mx, o));
    if (lid == 0) red[wid] = mx;
    __syncthreads();
    if (wid == 0) {
        float v = (lid < nw) ? red[lid] : -1e30f;
        for (int o = 16; o; o >>= 1) v = fmaxf(v, __shfl_xor_sync(0xffffffffu, v, o));
        if (lid == 0) red[0] = v;
    }
    __syncthreads();
    mx = red[0];
    __syncthreads();

    float sum = 0.f;
    for (int i = threadIdx.x; i < L; i += blockDim.x) {
        float e = __expf(row[i] - mx);
        row[i] = e;
        sum += e;
    }
    for (int o = 16; o; o >>= 1) sum += __shfl_xor_sync(0xffffffffu, sum, o);
    if (lid == 0) red[wid] = sum;
    __syncthreads();
    if (wid == 0) {
        float v = (lid < nw) ? red[lid] : 0.f;
        for (int o = 16; o; o >>= 1) v += __shfl_xor_sync(0xffffffffu, v, o);
        if (lid == 0) red[0] = v;
    }
    __syncthreads();
    const float inv = 1.f / red[0];
    for (int i = threadIdx.x; i < L; i += blockDim.x) row[i] *= inv;
}

// ---------------------------------------------------------------------------
// Host orchestration
// ---------------------------------------------------------------------------
static inline void run_gn(const float* in, float* out, const float* s, const float* b, int silu)
{
    gn_stats_kernel<<<256, 256>>>(in);
    gn_apply_kernel<<<4096, 256>>>(in, out, s, b, silu);
}

static inline void run_conv(const float* in, const float* w, const float* bias,
                            const float* resid, float* out)
{
    pad_split_kernel<<<(PADN * C_DIM + 255) / 256, 256>>>(in);
    wsplit_kernel<<<(C_DIM * C_DIM + 255) / 256, 256>>>(w);
    conv_wmma_kernel<<<dim3(4, 64), 256, CONV_SMEM_DYN>>>(bias, resid, out);
}

extern "C" void kernel_launch(void* const* d_in, const int* in_sizes, int n_in,
                              void* d_out, int out_size)
{
    (void)in_sizes; (void)n_in; (void)out_size;

    const float* x      = (const float*)d_in[0];
    const float* r0_n1s = (const float*)d_in[1];
    const float* r0_n1b = (const float*)d_in[2];
    const float* r0_w1  = (const float*)d_in[3];
    const float* r0_b1  = (const float*)d_in[4];
    const float* r0_n2s = (const float*)d_in[5];
    const float* r0_n2b = (const float*)d_in[6];
    const float* r0_w2  = (const float*)d_in[7];
    const float* r0_b2  = (const float*)d_in[8];
    const float* r1_n1s = (const float*)d_in[9];
    const float* r1_n1b = (const float*)d_in[10];
    const float* r1_w1  = (const float*)d_in[11];
    const float* r1_b1  = (const float*)d_in[12];
    const float* r1_n2s = (const float*)d_in[13];
    const float* r1_n2b = (const float*)d_in[14];
    const float* r1_w2  = (const float*)d_in[15];
    const float* r1_b2  = (const float*)d_in[16];
    const float* a_gns  = (const float*)d_in[17];
    const float* a_gnb  = (const float*)d_in[18];
    const float* a_wq   = (const float*)d_in[19];
    const float* a_bq   = (const float*)d_in[20];
    const float* a_wk   = (const float*)d_in[21];
    const float* a_bk   = (const float*)d_in[22];
    const float* a_wv   = (const float*)d_in[23];
    const float* a_bv   = (const float*)d_in[24];
    const float* a_wo   = (const float*)d_in[25];
    const float* a_bo   = (const float*)d_in[26];
    float* out = (float*)d_out;

    cudaFuncSetAttribute(conv_wmma_kernel, cudaFuncAttributeMaxDynamicSharedMemorySize,
                         CONV_SMEM_DYN);

    float *bufA, *bufB, *qb, *kb, *vb, *aob, *sb;
    cudaGetSymbolAddress((void**)&bufA, g_bufA);
    cudaGetSymbolAddress((void**)&bufB, g_bufB);
    cudaGetSymbolAddress((void**)&qb,   g_q);
    cudaGetSymbolAddress((void**)&kb,   g_k);
    cudaGetSymbolAddress((void**)&vb,   g_v);
    cudaGetSymbolAddress((void**)&aob,  g_ao);
    cudaGetSymbolAddress((void**)&sb,   g_scores);

    const float att_scale = 0.04419417382415922f;   // 512^-0.5

    // ---------------- resnet block 0 ----------------
    run_gn(x, bufA, r0_n1s, r0_n1b, 1);
    run_conv(bufA, r0_w1, r0_b1, nullptr, bufB);
    run_gn(bufB, bufA, r0_n2s, r0_n2b, 1);
    run_conv(bufA, r0_w2, r0_b2, x, bufB);                 // bufB = h0

    // ---------------- attention ----------------
    run_gn(bufB, bufA, a_gns, a_gnb, 0);                   // bufA = xn (c,s)
    {
        dim3 g(C_DIM / 128, SPATIAL / 128);
        gemm128_kernel<1, 1, 0><<<g, 256>>>(bufA, a_wq, qb, C_DIM, SPATIAL, C_DIM, C_DIM,
                                            1.f, nullptr, a_bq, nullptr);
        gemm128_kernel<1, 1, 0><<<g, 256>>>(bufA, a_wk, kb, C_DIM, SPATIAL, C_DIM, C_DIM,
                                            1.f, nullptr, a_bk, nullptr);
        gemm128_kernel<1, 1, 0><<<g, 256>>>(bufA, a_wv, vb, C_DIM, SPATIAL, C_DIM, C_DIM,
                                            1.f, nullptr, a_bv, nullptr);
    }
    {
        dim3 g(SPATIAL / 128, SPATIAL / 128);
        gemm128_kernel<0, 1, 2><<<g, 256>>>(qb, kb, sb, C_DIM, C_DIM, C_DIM, SPATIAL,
                                            att_scale, nullptr, nullptr, nullptr);
    }
    softmax_kernel<<<SPATIAL, 256>>>(sb);
    {
        dim3 g(C_DIM / 128, SPATIAL / 128);
        gemm128_kernel<0, 0, 1><<<g, 256>>>(sb, vb, aob, SPATIAL, SPATIAL, C_DIM, C_DIM,
                                            1.f, nullptr, nullptr, nullptr);
    }
    {
        dim3 g(SPATIAL / 128, C_DIM / 128);
        gemm128_kernel<0, 1, 0><<<g, 256>>>(a_wo, aob, bufA, C_DIM, C_DIM, C_DIM, SPATIAL,
                                            1.f, a_bo, nullptr, bufB);   // bufA = h1
    }

    // ---------------- resnet block 1 ----------------
    run_gn(bufA, bufB, r1_n1s, r1_n1b, 1);
    run_conv(bufB, r1_w1, r1_b1, nullptr, bufB);
    run_gn(bufB, qb, r1_n2s, r1_n2b, 1);
    run_conv(qb, r1_w2, r1_b2, bufA, out);                 // out = h1 + conv
}

// round 15
// speedup vs baseline: 1.6693x; 1.0340x over previous
#include <cuda_runtime.h>
#include <cuda_bf16.h>
#include <mma.h>
#include <math.h>

using namespace nvcuda;

// ---------------------------------------------------------------------------
// Problem constants
// ---------------------------------------------------------------------------
#define C_DIM   512
#define TDIM    8
#define HDIM    32
#define WDIM    32
#define SPATIAL 8192            // T*H*W
#define GROUPS  32
#define TP      10              // padded T (2,0)
#define HP      34              // padded H (1,1)
#define WP      34              // padded W (1,1)
#define PADN    (TP*HP*WP)      // 11560
#define NTAPS   27
#define CI_CHUNK 64
#define LDAB    72              // conv smem row stride (bf16 elems)
#define LDK     40              // gemm smem row stride (bf16 elems), 32+8

// ---------------------------------------------------------------------------
// bf16 split helper
// ---------------------------------------------------------------------------
__device__ __forceinline__ void bsplit(float v, __nv_bfloat16& hi, __nv_bfloat16& lo) {
    hi = __float2bfloat16(v);
    lo = __float2bfloat16(v - __bfloat162float(hi));
}

// ---------------------------------------------------------------------------
// Scratch (device globals; no runtime allocation allowed)
// ---------------------------------------------------------------------------
__device__ float g_bufA[C_DIM * SPATIAL];
__device__ float g_bufB[C_DIM * SPATIAL];
__device__ float g_q[SPATIAL * C_DIM];
__device__ float g_k[SPATIAL * C_DIM];
__device__ float g_v[SPATIAL * C_DIM];
__device__ float g_ao[SPATIAL * C_DIM];
__device__ float g_part[256 * 2];                          // GN partials
__device__ float g_scores[(size_t)SPATIAL * SPATIAL];      // 256 MB
// conv bf16 split operands
__device__ __nv_bfloat16 g_phiT[(size_t)PADN * C_DIM];     // P^T hi  [sp][ci]
__device__ __nv_bfloat16 g_ploT[(size_t)PADN * C_DIM];     // P^T lo
__device__ __nv_bfloat16 g_wtHi[(size_t)NTAPS * C_DIM * C_DIM]; // [tap][co][ci]
__device__ __nv_bfloat16 g_wtLo[(size_t)NTAPS * C_DIM * C_DIM];

// ---------------------------------------------------------------------------
// GroupNorm pass 1 (unchanged, proven)
// ---------------------------------------------------------------------------
__global__ void gn_stats_kernel(const float* __restrict__ in)
{
    const int blk = blockIdx.x;
    const float4* p = (const float4*)(in + (size_t)blk * 16384);
    float sum = 0.f, sq = 0.f;
    for (int i = threadIdx.x; i < 4096; i += 256) {
        float4 v = p[i];
        sum += v.x + v.y + v.z + v.w;
        sq  += v.x*v.x + v.y*v.y + v.z*v.z + v.w*v.w;
    }
    __shared__ float ss[8], sg[8];
    for (int o = 16; o; o >>= 1) {
        sum += __shfl_xor_sync(0xffffffffu, sum, o);
        sq  += __shfl_xor_sync(0xffffffffu, sq,  o);
    }
    const int wid = threadIdx.x >> 5, lid = threadIdx.x & 31;
    if (lid == 0) { ss[wid] = sum; sg[wid] = sq; }
    __syncthreads();
    if (threadIdx.x == 0) {
        float a = 0.f, b = 0.f;
        for (int w = 0; w < 8; w++) { a += ss[w]; b += sg[w]; }
        g_part[blk * 2 + 0] = a;
        g_part[blk * 2 + 1] = b;
    }
}

// ---------------------------------------------------------------------------
// GroupNorm pass 2 (unchanged, proven)
// ---------------------------------------------------------------------------
__global__ void gn_apply_kernel(const float* __restrict__ in, float* __restrict__ out,
                                const float* __restrict__ scale, const float* __restrict__ bias,
                                int do_silu)
{
    const int i4 = blockIdx.x * 256 + threadIdx.x;
    const int base = i4 * 4;
    const int c = base >> 13;
    const int group = c >> 4;

    __shared__ float smu, srstd;
    if (threadIdx.x == 0) {
        float s = 0.f, q = 0.f;
        for (int k = 0; k < 8; k++) {
            s += g_part[(group * 8 + k) * 2 + 0];
            q += g_part[(group * 8 + k) * 2 + 1];
        }
        const float mu = s * (1.f / 131072.f);
        smu = mu;
        srstd = rsqrtf(q * (1.f / 131072.f) - mu * mu + 1e-6f);
    }
    __syncthreads();
    const float mu = smu, rstd = srstd;
    const float sc = scale[c], bi = bias[c];

    float4 v = ((const float4*)in)[i4];
    float r[4] = {v.x, v.y, v.z, v.w};
#pragma unroll
    for (int j = 0; j < 4; j++) {
        float t = (r[j] - mu) * rstd * sc + bi;
        if (do_silu) t = t / (1.f + __expf(-t));
        r[j] = t;
    }
    ((float4*)out)[i4] = make_float4(r[0], r[1], r[2], r[3]);
}

// ---------------------------------------------------------------------------
// pad + transpose + bf16-split (unchanged, proven)
// ---------------------------------------------------------------------------
__global__ void pad_split_kernel(const float* __restrict__ in)
{
    const size_t id = (size_t)blockIdx.x * 256 + threadIdx.x;
    if (id >= (size_t)PADN * C_DIM) return;
    const int ci = (int)(id & 511);
    int sp = (int)(id >> 9);
    int tp = sp / (HP * WP); int r = sp - tp * (HP * WP);
    int yp = r / WP; int xp = r - yp * WP;
    int t = tp - 2; if (t < 0) t = 0;
    int y = yp - 1; if (y < 0) y = 0; if (y > HDIM - 1) y = HDIM - 1;
    int x = xp - 1; if (x < 0) x = 0; if (x > WDIM - 1) x = WDIM - 1;
    float v = in[(size_t)ci * SPATIAL + t * 1024 + y * 32 + x];
    __nv_bfloat16 hi, lo; bsplit(v, hi, lo);
    g_phiT[id] = hi;
    g_ploT[id] = lo;
}

// ---------------------------------------------------------------------------
// Weight transpose + bf16-split (unchanged, proven)
// ---------------------------------------------------------------------------
__global__ void wsplit_kernel(const float* __restrict__ W)
{
    const int id = blockIdx.x * 256 + threadIdx.x;   // co*512+ci
    if (id >= C_DIM * C_DIM) return;
    const float* src = W + (size_t)id * NTAPS;
#pragma unroll
    for (int tap = 0; tap < NTAPS; tap++) {
        __nv_bfloat16 hi, lo; bsplit(src[tap], hi, lo);
        const size_t o = (size_t)tap * (C_DIM * C_DIM) + id;
        g_wtHi[o] = hi;
        g_wtLo[o] = lo;
    }
}

// ---------------------------------------------------------------------------
// WMMA conv (unchanged, proven R12: 3-term bf16 split, 8 warps 64x32)
// ---------------------------------------------------------------------------
#define CONV_SMEM_DYN (4 * 128 * LDAB * 2)

__global__ __launch_bounds__(256)
void conv_wmma_kernel(const float* __restrict__ bias, const float* __restrict__ resid,
                      float* __restrict__ out)
{
    extern __shared__ char dsm[];
    __nv_bfloat16* sAhi = (__nv_bfloat16*)dsm;
    __nv_bfloat16* sAlo = sAhi + 128 * LDAB;
    __nv_bfloat16* sBhi = sAlo + 128 * LDAB;
    __nv_bfloat16* sBlo = sBhi + 128 * LDAB;
    float* sC = (float*)dsm;

    const int tid = threadIdx.x;
    const int wid = tid >> 5;
    const int co0 = blockIdx.x * 128;
    const int t0  = blockIdx.y >> 3;
    const int y0  = (blockIdx.y & 7) * 4;
    const int wm  = (wid & 1) * 64;
    const int wn  = (wid >> 1) * 32;

    wmma::fragment<wmma::accumulator, 16, 16, 16, float> acc[4][2];
#pragma unroll
    for (int i = 0; i < 4; i++)
#pragma unroll
        for (int j = 0; j < 2; j++) wmma::fill_fragment(acc[i][j], 0.f);

    const int rowT  = tid & 127;
    const int which = tid >> 7;
    const __nv_bfloat16* Asrc = which ? g_wtLo : g_wtHi;
    const __nv_bfloat16* Bsrc = which ? g_ploT : g_phiT;
    __nv_bfloat16* Adst = (which ? sAlo : sAhi) + rowT * LDAB;
    __nv_bfloat16* Bdst = (which ? sBlo : sBhi) + rowT * LDAB;
    const int yy = rowT >> 5, xx = rowT & 31;

    for (int tap = 0; tap < NTAPS; tap++) {
        const int kt = tap / 9, rr = tap - kt * 9;
        const int ky = rr / 3,  kx = rr - ky * 3;
        const int spbase = (t0 + kt) * (HP * WP) + (y0 + ky) * WP + kx;
        const size_t aTap = (size_t)tap * (C_DIM * C_DIM) + (size_t)(co0 + rowT) * C_DIM;
        const size_t bRow = (size_t)(spbase + yy * WP + xx) * C_DIM;

        for (int ci0 = 0; ci0 < C_DIM; ci0 += CI_CHUNK) {
            __syncthreads();
            const uint4* ag = (const uint4*)(Asrc + aTap + ci0);
            const uint4* bg = (const uint4*)(Bsrc + bRow + ci0);
            uint4* ad = (uint4*)Adst;
            uint4* bd = (uint4*)Bdst;
#pragma unroll
            for (int j = 0; j < 8; j++) ad[j] = ag[j];
#pragma unroll
            for (int j = 0; j < 8; j++) bd[j] = bg[j];
            __syncthreads();

#pragma unroll
            for (int term = 0; term < 3; term++) {
                const __nv_bfloat16* Ap = (term == 2) ? sAlo : sAhi;
                const __nv_bfloat16* Bp = (term == 1) ? sBlo : sBhi;
#pragma unroll
                for (int kk = 0; kk < 4; kk++) {
                    wmma::fragment<wmma::matrix_a, 16, 16, 16, __nv_bfloat16,
                                   wmma::row_major> a_frag[4];
                    wmma::fragment<wmma::matrix_b, 16, 16, 16, __nv_bfloat16,
                                   wmma::col_major> b_frag[2];
#pragma unroll
                    for (int i = 0; i < 4; i++)
                        wmma::load_matrix_sync(a_frag[i],
                            Ap + (wm + i * 16) * LDAB + kk * 16, LDAB);
#pragma unroll
                    for (int j = 0; j < 2; j++)
                        wmma::load_matrix_sync(b_frag[j],
                            Bp + (wn + j * 16) * LDAB + kk * 16, LDAB);
#pragma unroll
                    for (int i = 0; i < 4; i++)
#pragma unroll
                        for (int j = 0; j < 2; j++)
                            wmma::mma_sync(acc[i][j], a_frag[i], b_frag[j], acc[i][j]);
                }
            }
        }
    }

    __syncthreads();
#pragma unroll
    for (int i = 0; i < 4; i++)
#pragma unroll
        for (int j = 0; j < 2; j++)
            wmma::store_matrix_sync(sC + (wm + i * 16) * 128 + wn + j * 16,
                                    acc[i][j], 128, wmma::mem_row_major);
    __syncthreads();

    for (int idx = tid; idx < 128 * 32; idx += 256) {
        const int row = idx >> 5;
        const int c4  = idx & 31;
        float4 v = ((const float4*)(sC + row * 128))[c4];
        const int co = co0 + row;
        const float bb = bias[co];
        v.x += bb; v.y += bb; v.z += bb; v.w += bb;
        const size_t o = (size_t)co * SPATIAL + t0 * 1024 + y0 * 32 + c4 * 4;
        if (resid) {
            const float4 rv = *(const float4*)&resid[o];
            v.x += rv.x; v.y += rv.y; v.z += rv.z; v.w += rv.w;
        }
        *(float4*)&out[o] = v;
    }
}

// ---------------------------------------------------------------------------
// WMMA split GEMM: C[m,n] = alpha * sum_k A(m,k) B(k,n) (+biasM/biasN/resid)
// fp32 inputs converted to bf16 hi/lo on the fly in the smem fill;
// 3-term split product, fp32 accumulators. Tile 128x128, K-chunk 32.
// TA=0: A row-major (m,k), A[m*lda+k].  TA=1: A is (k,m), A[k*lda+m].
// TB=0: B (k,n), B[k*ldb+n].            TB=1: B (n,k), B[n*ldb+k].
// MODE 0 plain; 1 K clipped to causal prefix of m-tile; 2 skip masked tile.
// M,N multiples of 128; K (and clip) multiples of 32.
// ---------------------------------------------------------------------------
#define GEMM_SMEM_DYN 65536   // max(4*128*LDK*2 = 40960, epilogue 128*128*4)

template<int TA, int TB, int MODE>
__global__ __launch_bounds__(256)
void wmma_gemm_kernel(const float* __restrict__ A, const float* __restrict__ B,
                      float* __restrict__ C,
                      int K, int lda, int ldb, int ldc,
                      float alpha,
                      const float* __restrict__ biasM, const float* __restrict__ biasN,
                      const float* __restrict__ resid)
{
    const int n0 = blockIdx.x * 128;
    const int m0 = blockIdx.y * 128;
    if (MODE == 2 && ((n0 >> 10) > (m0 >> 10))) return;
    int Keff = K;
    if (MODE == 1) {
        const int lim = ((m0 >> 10) + 1) << 10;
        if (lim < Keff) Keff = lim;
    }

    extern __shared__ char dsm[];
    __nv_bfloat16* sAhi = (__nv_bfloat16*)dsm;
    __nv_bfloat16* sAlo = sAhi + 128 * LDK;
    __nv_bfloat16* sBhi = sAlo + 128 * LDK;
    __nv_bfloat16* sBlo = sBhi + 128 * LDK;
    float* sC = (float*)dsm;

    const int tid = threadIdx.x;
    const int wid = tid >> 5;
    const int wm  = (wid & 1) * 64;
    const int wn  = (wid >> 1) * 32;

    wmma::fragment<wmma::accumulator, 16, 16, 16, float> acc[4][2];
#pragma unroll
    for (int i = 0; i < 4; i++)
#pragma unroll
        for (int j = 0; j < 2; j++) wmma::fill_fragment(acc[i][j], 0.f);

    for (int k0 = 0; k0 < Keff; k0 += 32) {
        __syncthreads();
        // ---- fill A ----
        if (TA == 0) {
            const int row = tid >> 1;
            const int c0  = (tid & 1) * 16;
            const float4* src = (const float4*)&A[(size_t)(m0 + row) * lda + k0 + c0];
            __nv_bfloat16* dh = sAhi + row * LDK + c0;
            __nv_bfloat16* dl = sAlo + row * LDK + c0;
#pragma unroll
            for (int j = 0; j < 4; j++) {
                float4 f = src[j];
                bsplit(f.x, dh[j*4+0], dl[j*4+0]);
                bsplit(f.y, dh[j*4+1], dl[j*4+1]);
                bsplit(f.z, dh[j*4+2], dl[j*4+2]);
                bsplit(f.w, dh[j*4+3], dl[j*4+3]);
            }
        } else {
            const int kk2  = tid >> 3;            // 0..31
            const int mcol = (tid & 7) * 16;
            const float4* src = (const float4*)&A[(size_t)(k0 + kk2) * lda + m0 + mcol];
#pragma unroll
            for (int j = 0; j < 4; j++) {
                float4 f = src[j];
                const int mb = mcol + j * 4;
                bsplit(f.x, sAhi[(mb+0)*LDK + kk2], sAlo[(mb+0)*LDK + kk2]);
                bsplit(f.y, sAhi[(mb+1)*LDK + kk2], sAlo[(mb+1)*LDK + kk2]);
                bsplit(f.z, sAhi[(mb+2)*LDK + kk2], sAlo[(mb+2)*LDK + kk2]);
                bsplit(f.w, sAhi[(mb+3)*LDK + kk2], sAlo[(mb+3)*LDK + kk2]);
            }
        }
        // ---- fill B (smem layout [n][k]) ----
        if (TB == 1) {
            const int row = tid >> 1;
            const int c0  = (tid & 1) * 16;
            const float4* src = (const float4*)&B[(size_t)(n0 + row) * ldb + k0 + c0];
            __nv_bfloat16* dh = sBhi + row * LDK + c0;
            __nv_bfloat16* dl = sBlo + row * LDK + c0;
#pragma unroll
            for (int j = 0; j < 4; j++) {
                float4 f = src[j];
                bsplit(f.x, dh[j*4+0], dl[j*4+0]);
                bsplit(f.y, dh[j*4+1], dl[j*4+1]);
                bsplit(f.z, dh[j*4+2], dl[j*4+2]);
                bsplit(f.w, dh[j*4+3], dl[j*4+3]);
            }
        } else {
            const int kk2  = tid >> 3;
            const int ncol = (tid & 7) * 16;
            const float4* src = (const float4*)&B[(size_t)(k0 + kk2) * ldb + n0 + ncol];
#pragma unroll
            for (int j = 0; j < 4; j++) {
                float4 f = src[j];
                const int nb = ncol + j * 4;
                bsplit(f.x, sBhi[(nb+0)*LDK + kk2], sBlo[(nb+0)*LDK + kk2]);
                bsplit(f.y, sBhi[(nb+1)*LDK + kk2], sBlo[(nb+1)*LDK + kk2]);
                bsplit(f.z, sBhi[(nb+2)*LDK + kk2], sBlo[(nb+2)*LDK + kk2]);
                bsplit(f.w, sBhi[(nb+3)*LDK + kk2], sBlo[(nb+3)*LDK + kk2]);
            }
        }
        __syncthreads();

        // ---- 3-term split MMA ----
#pragma unroll
        for (int term = 0; term < 3; term++) {
            const __nv_bfloat16* Ap = (term == 2) ? sAlo : sAhi;
            const __nv_bfloat16* Bp = (term == 1) ? sBlo : sBhi;
#pragma unroll
            for (int kk = 0; kk < 2; kk++) {
                wmma::fragment<wmma::matrix_a, 16, 16, 16, __nv_bfloat16,
                               wmma::row_major> a_frag[4];
                wmma::fragment<wmma::matrix_b, 16, 16, 16, __nv_bfloat16,
                               wmma::col_major> b_frag[2];
#pragma unroll
                for (int i = 0; i < 4; i++)
                    wmma::load_matrix_sync(a_frag[i],
                        Ap + (wm + i * 16) * LDK + kk * 16, LDK);
#pragma unroll
                for (int j = 0; j < 2; j++)
                    wmma::load_matrix_sync(b_frag[j],
                        Bp + (wn + j * 16) * LDK + kk * 16, LDK);
#pragma unroll
                for (int i = 0; i < 4; i++)
#pragma unroll
                    for (int j = 0; j < 2; j++)
                        wmma::mma_sync(acc[i][j], a_frag[i], b_frag[j], acc[i][j]);
            }
        }
    }

    // ---- epilogue ----
    __syncthreads();
#pragma unroll
    for (int i = 0; i < 4; i++)
#pragma unroll
        for (int j = 0; j < 2; j++)
            wmma::store_matrix_sync(sC + (wm + i * 16) * 128 + wn + j * 16,
                                    acc[i][j], 128, wmma::mem_row_major);
    __syncthreads();

    for (int idx = tid; idx < 128 * 32; idx += 256) {
        const int row = idx >> 5;
        const int c4  = idx & 31;
        float4 v = ((const float4*)(sC + row * 128))[c4];
        const int m = m0 + row;
        const float bm = biasM ? biasM[m] : 0.f;
        v.x = v.x * alpha + bm;
        v.y = v.y * alpha + bm;
        v.z = v.z * alpha + bm;
        v.w = v.w * alpha + bm;
        if (biasN) {
            const float4 bn = *(const float4*)&biasN[n0 + c4 * 4];
            v.x += bn.x; v.y += bn.y; v.z += bn.z; v.w += bn.w;
        }
        const size_t o = (size_t)m * ldc + n0 + c4 * 4;
        if (resid) {
            const float4 rv = *(const float4*)&resid[o];
            v.x += rv.x; v.y += rv.y; v.z += rv.z; v.w += rv.w;
        }
        *(float4*)&C[o] = v;
    }
}

// ---------------------------------------------------------------------------
// Row softmax over causal prefix (unchanged, proven)
// ---------------------------------------------------------------------------
__global__ void softmax_kernel(float* __restrict__ S)
{
    const int q = blockIdx.x;
    const int L = ((q >> 10) + 1) << 10;
    float* row = S + (size_t)q * SPATIAL;
    __shared__ float red[32];
    const int wid = threadIdx.x >> 5, lid = threadIdx.x & 31;
    const int nw = blockDim.x >> 5;

    float mx = -1e30f;
    for (int i = threadIdx.x; i < L; i += blockDim.x) mx = fmaxf(mx, row[i]);
    for (int o = 16; o; o >>= 1) mx = fmaxf(mx, __shfl_xor_sync(0xffffffffu, mx, o));
    if (lid == 0) red[wid] = mx;
    __syncthreads();
    if (wid == 0) {
        float v = (lid < nw) ? red[lid] : -1e30f;
        for (int o = 16; o; o >>= 1) v = fmaxf(v, __shfl_xor_sync(0xffffffffu, v, o));
        if (lid == 0) red[0] = v;
    }
    __syncthreads();
    mx = red[0];
    __syncthreads();

    float sum = 0.f;
    for (int i = threadIdx.x; i < L; i += blockDim.x) {
        float e = __expf(row[i] - mx);
        row[i] = e;
        sum += e;
    }
    for (int o = 16; o; o >>= 1) sum += __shfl_xor_sync(0xffffffffu, sum, o);
    if (lid == 0) red[wid] = sum;
    __syncthreads();
    if (wid == 0) {
        float v = (lid < nw) ? red[lid] : 0.f;
        for (int o = 16; o; o >>= 1) v += __shfl_xor_sync(0xffffffffu, v, o);
        if (lid == 0) red[0] = v;
    }
    __syncthreads();
    const float inv = 1.f / red[0];
    for (int i = threadIdx.x; i < L; i += blockDim.x) row[i] *= inv;
}

// ---------------------------------------------------------------------------
// Host orchestration
// ---------------------------------------------------------------------------
static inline void run_gn(const float* in, float* out, const float* s, const float* b, int silu)
{
    gn_stats_kernel<<<256, 256>>>(in);
    gn_apply_kernel<<<4096, 256>>>(in, out, s, b, silu);
}

static inline void run_conv(const float* in, const float* w, const float* bias,
                            const float* resid, float* out)
{
    pad_split_kernel<<<(PADN * C_DIM + 255) / 256, 256>>>(in);
    wsplit_kernel<<<(C_DIM * C_DIM + 255) / 256, 256>>>(w);
    conv_wmma_kernel<<<dim3(4, 64), 256, CONV_SMEM_DYN>>>(bias, resid, out);
}

extern "C" void kernel_launch(void* const* d_in, const int* in_sizes, int n_in,
                              void* d_out, int out_size)
{
    (void)in_sizes; (void)n_in; (void)out_size;

    const float* x      = (const float*)d_in[0];
    const float* r0_n1s = (const float*)d_in[1];
    const float* r0_n1b = (const float*)d_in[2];
    const float* r0_w1  = (const float*)d_in[3];
    const float* r0_b1  = (const float*)d_in[4];
    const float* r0_n2s = (const float*)d_in[5];
    const float* r0_n2b = (const float*)d_in[6];
    const float* r0_w2  = (const float*)d_in[7];
    const float* r0_b2  = (const float*)d_in[8];
    const float* r1_n1s = (const float*)d_in[9];
    const float* r1_n1b = (const float*)d_in[10];
    const float* r1_w1  = (const float*)d_in[11];
    const float* r1_b1  = (const float*)d_in[12];
    const float* r1_n2s = (const float*)d_in[13];
    const float* r1_n2b = (const float*)d_in[14];
    const float* r1_w2  = (const float*)d_in[15];
    const float* r1_b2  = (const float*)d_in[16];
    const float* a_gns  = (const float*)d_in[17];
    const float* a_gnb  = (const float*)d_in[18];
    const float* a_wq   = (const float*)d_in[19];
    const float* a_bq   = (const float*)d_in[20];
    const float* a_wk   = (const float*)d_in[21];
    const float* a_bk   = (const float*)d_in[22];
    const float* a_wv   = (const float*)d_in[23];
    const float* a_bv   = (const float*)d_in[24];
    const float* a_wo   = (const float*)d_in[25];
    const float* a_bo   = (const float*)d_in[26];
    float* out = (float*)d_out;

    cudaFuncSetAttribute(conv_wmma_kernel, cudaFuncAttributeMaxDynamicSharedMemorySize,
                         CONV_SMEM_DYN);
    cudaFuncSetAttribute(wmma_gemm_kernel<1,1,0>, cudaFuncAttributeMaxDynamicSharedMemorySize,
                         GEMM_SMEM_DYN);
    cudaFuncSetAttribute(wmma_gemm_kernel<0,1,2>, cudaFuncAttributeMaxDynamicSharedMemorySize,
                         GEMM_SMEM_DYN);
    cudaFuncSetAttribute(wmma_gemm_kernel<0,0,1>, cudaFuncAttributeMaxDynamicSharedMemorySize,
                         GEMM_SMEM_DYN);
    cudaFuncSetAttribute(wmma_gemm_kernel<0,1,0>, cudaFuncAttributeMaxDynamicSharedMemorySize,
                         GEMM_SMEM_DYN);

    float *bufA, *bufB, *qb, *kb, *vb, *aob, *sb;
    cudaGetSymbolAddress((void**)&bufA, g_bufA);
    cudaGetSymbolAddress((void**)&bufB, g_bufB);
    cudaGetSymbolAddress((void**)&qb,   g_q);
    cudaGetSymbolAddress((void**)&kb,   g_k);
    cudaGetSymbolAddress((void**)&vb,   g_v);
    cudaGetSymbolAddress((void**)&aob,  g_ao);
    cudaGetSymbolAddress((void**)&sb,   g_scores);

    const float att_scale = 0.04419417382415922f;   // 512^-0.5

    // ---------------- resnet block 0 ----------------
    run_gn(x, bufA, r0_n1s, r0_n1b, 1);
    run_conv(bufA, r0_w1, r0_b1, nullptr, bufB);
    run_gn(bufB, bufA, r0_n2s, r0_n2b, 1);
    run_conv(bufA, r0_w2, r0_b2, x, bufB);                 // bufB = h0

    // ---------------- attention ----------------
    run_gn(bufB, bufA, a_gns, a_gnb, 0);                   // bufA = xn (c,s)
    {
        dim3 g(C_DIM / 128, SPATIAL / 128);
        wmma_gemm_kernel<1, 1, 0><<<g, 256, GEMM_SMEM_DYN>>>(
            bufA, a_wq, qb, C_DIM, SPATIAL, C_DIM, C_DIM, 1.f, nullptr, a_bq, nullptr);
        wmma_gemm_kernel<1, 1, 0><<<g, 256, GEMM_SMEM_DYN>>>(
            bufA, a_wk, kb, C_DIM, SPATIAL, C_DIM, C_DIM, 1.f, nullptr, a_bk, nullptr);
        wmma_gemm_kernel<1, 1, 0><<<g, 256, GEMM_SMEM_DYN>>>(
            bufA, a_wv, vb, C_DIM, SPATIAL, C_DIM, C_DIM, 1.f, nullptr, a_bv, nullptr);
    }
    {
        dim3 g(SPATIAL / 128, SPATIAL / 128);
        wmma_gemm_kernel<0, 1, 2><<<g, 256, GEMM_SMEM_DYN>>>(
            qb, kb, sb, C_DIM, C_DIM, C_DIM, SPATIAL, att_scale, nullptr, nullptr, nullptr);
    }
    softmax_kernel<<<SPATIAL, 256>>>(sb);
    {
        dim3 g(C_DIM / 128, SPATIAL / 128);
        wmma_gemm_kernel<0, 0, 1><<<g, 256, GEMM_SMEM_DYN>>>(
            sb, vb, aob, SPATIAL, SPATIAL, C_DIM, C_DIM, 1.f, nullptr, nullptr, nullptr);
    }
    {
        dim3 g(SPATIAL / 128, C_DIM / 128);
        wmma_gemm_kernel<0, 1, 0><<<g, 256, GEMM_SMEM_DYN>>>(
            a_wo, aob, bufA, C_DIM, C_DIM, C_DIM, SPATIAL, 1.f, a_bo, nullptr, bufB); // bufA = h1
    }

    // ---------------- resnet block 1 ----------------
    run_gn(bufA, bufB, r1_n1s, r1_n1b, 1);
    run_conv(bufB, r1_w1, r1_b1, nullptr, bufB);
    run_gn(bufB, qb, r1_n2s, r1_n2b, 1);
    run_conv(qb, r1_w2, r1_b2, bufA, out);                 // out = h1 + conv
}